// round 1
// baseline (speedup 1.0000x reference)
#include <cuda_runtime.h>
#include <math.h>

// ---------------- problem constants ----------------
constexpr int BB  = 2048;
constexpr int SS  = 64;
constexpr int CC  = 142;
constexpr int DD  = 256;
constexpr int HHD = 8;    // heads
constexpr int DHH = 32;   // head dim
constexpr int FFD = 512;
constexpr int LLY = 3;
constexpr int EED = 128;  // z_e dim
constexpr int KKC = 1024; // codebook size
constexpr int TTT = 65;   // S + 1
#define EPSLN 1e-5f

// ---------------- scratch (device globals; no allocs allowed) ----------------
__device__ float g_h   [(size_t)BB * TTT * DD];        // 136 MB
__device__ float g_qkv [(size_t)BB * TTT * 3 * DD];    // 409 MB
__device__ float g_o   [(size_t)BB * TTT * DD];        // 136 MB
__device__ float g_ff  [(size_t)BB * TTT * FFD];       // 272 MB
__device__ float g_cls [BB * DD];
__device__ float g_ze  [BB * EED];
__device__ float g_zqst[BB * EED];
__device__ float g_d1  [BB * DD];
__device__ float g_d2  [BB * EED];
__device__ float g_lossrow[BB];
__device__ float g_hist[KKC];
__device__ int   g_idx [BB];
__device__ float g_pe  [SS * DD];

// ---------------- helpers ----------------
__device__ __forceinline__ float gelu_exact(float v) {
    return 0.5f * v * (1.f + erff(v * 0.70710678118654752f));
}

// ---------------- PE table (double precision trig for accuracy) ----------------
__global__ void pe_init_kernel() {
    int i = blockIdx.x * blockDim.x + threadIdx.x;
    if (i < SS * DD) {
        int s = i >> 8, n = i & 255;
        double div = exp((double)(n & ~1) * (-9.210340371976184 / 256.0));
        double v = (n & 1) ? cos((double)s * div) : sin((double)s * div);
        g_pe[i] = (float)v;
    }
}

// ---------------- zero init (d_out + histogram) ----------------
__global__ void zero_kernel(float* out, int out_size) {
    int i = blockIdx.x * blockDim.x + threadIdx.x;
    if (i < out_size) out[i] = 0.f;
    if (i < KKC) g_hist[i] = 0.f;
}

// ---------------- cls token broadcast into h row 0 of each batch ----------------
__global__ void cls_fill_kernel(const float* __restrict__ cls) {
    int i = blockIdx.x * blockDim.x + threadIdx.x;
    if (i < BB * DD) {
        int b = i >> 8, d = i & 255;
        g_h[(size_t)b * TTT * DD + d] = cls[d];
    }
}

// ---------------- generic SGEMM: C = A[M,K] * W[N,K]^T + bias, epilogues ----------------
// EPI: 0 = bias, 1 = bias+gelu, 2 = bias+residual (in-place ok), 3 = bias+PE, scatter to h rows (m + m/64 + 1)
template <int EPI>
__global__ __launch_bounds__(256) void gemm128(
    const float* __restrict__ A, const float* __restrict__ W,
    const float* __restrict__ bias, const float* __restrict__ resid,
    float* __restrict__ C, int M, int N, int K)
{
    __shared__ float As[16][132];
    __shared__ float Bs[16][132];
    const int tid = threadIdx.x;
    const int tx = tid & 15, ty = tid >> 4;
    const int m0 = blockIdx.x * 128, n0 = blockIdx.y * 128;

    float acc[8][8];
#pragma unroll
    for (int i = 0; i < 8; ++i)
#pragma unroll
        for (int j = 0; j < 8; ++j) acc[i][j] = 0.f;

    const int lk = tid & 15;   // k within tile
    const int lr = tid >> 4;   // 0..15 row group

    for (int k0 = 0; k0 < K; k0 += 16) {
        const int kg = k0 + lk;
        const bool kin = (kg < K);
#pragma unroll
        for (int it = 0; it < 8; ++it) {
            int r = lr + it * 16;
            As[lk][r] = kin ? A[(size_t)(m0 + r) * K + kg] : 0.f;
            Bs[lk][r] = kin ? W[(size_t)(n0 + r) * K + kg] : 0.f;
        }
        __syncthreads();
#pragma unroll
        for (int kk = 0; kk < 16; ++kk) {
            float a[8], bb[8];
#pragma unroll
            for (int i = 0; i < 8; ++i) a[i] = As[kk][ty + 16 * i];
#pragma unroll
            for (int j = 0; j < 8; ++j) bb[j] = Bs[kk][tx + 16 * j];
#pragma unroll
            for (int i = 0; i < 8; ++i)
#pragma unroll
                for (int j = 0; j < 8; ++j)
                    acc[i][j] = fmaf(a[i], bb[j], acc[i][j]);
        }
        __syncthreads();
    }

#pragma unroll
    for (int i = 0; i < 8; ++i) {
        const int m = m0 + ty + 16 * i;
#pragma unroll
        for (int j = 0; j < 8; ++j) {
            const int n = n0 + tx + 16 * j;
            float v = acc[i][j] + bias[n];
            if (EPI == 1) {
                C[(size_t)m * N + n] = gelu_exact(v);
            } else if (EPI == 2) {
                v += resid[(size_t)m * N + n];
                C[(size_t)m * N + n] = v;
            } else if (EPI == 3) {
                const int bi = m >> 6;     // batch
                const int s  = m & 63;     // seq pos
                v += g_pe[s * DD + n];
                C[(size_t)(m + bi + 1) * N + n] = v;   // scatter past cls row
            } else {
                C[(size_t)m * N + n] = v;
            }
        }
    }
}

// ---------------- attention: one block per (b, head); whole T=65 in smem ----------------
__global__ __launch_bounds__(128) void attn_kernel() {
    const int bh = blockIdx.x;
    const int b = bh >> 3, hd = bh & 7;
    __shared__ float Ks[TTT][DHH + 1];
    __shared__ float Vs[TTT][DHH + 1];
    __shared__ float Ps[TTT][TTT + 1];
    const int tid = threadIdx.x;
    const size_t base = (size_t)b * TTT * 768;

    for (int i = tid; i < TTT * DHH; i += 128) {
        int t = i >> 5, d = i & 31;
        size_t rb = base + (size_t)t * 768 + hd * 32 + d;
        Ks[t][d] = g_qkv[rb + 256];
        Vs[t][d] = g_qkv[rb + 512];
    }
    __syncthreads();

    if (tid < TTT) {
        const int qi = tid;
        float q[DHH];
        const size_t qb = base + (size_t)qi * 768 + hd * 32;
#pragma unroll
        for (int d = 0; d < DHH; ++d) q[d] = g_qkv[qb + d];

        float mx = -1e30f;
        for (int ki = 0; ki < TTT; ++ki) {
            float s = 0.f;
#pragma unroll
            for (int d = 0; d < DHH; ++d) s = fmaf(q[d], Ks[ki][d], s);
            s *= 0.17677669529663687f;  // 1/sqrt(32)
            Ps[qi][ki] = s;
            mx = fmaxf(mx, s);
        }
        float sum = 0.f;
        for (int ki = 0; ki < TTT; ++ki) {
            float e = expf(Ps[qi][ki] - mx);
            Ps[qi][ki] = e;
            sum += e;
        }
        const float inv = 1.f / sum;

        float acc[DHH];
#pragma unroll
        for (int d = 0; d < DHH; ++d) acc[d] = 0.f;
        for (int ki = 0; ki < TTT; ++ki) {
            float p = Ps[qi][ki];
#pragma unroll
            for (int d = 0; d < DHH; ++d) acc[d] = fmaf(p, Vs[ki][d], acc[d]);
        }
        const size_t ob = ((size_t)b * TTT + qi) * DD + hd * 32;
#pragma unroll
        for (int d = 0; d < DHH; ++d) g_o[ob + d] = acc[d] * inv;
    }
}

// ---------------- LayerNorm over last dim (256), optional GELU after ----------------
template <int GELU>
__global__ __launch_bounds__(256) void ln_kernel(
    const float* __restrict__ in, float* __restrict__ out,
    const float* __restrict__ gamma, const float* __restrict__ beta,
    size_t inStride, size_t outStride)
{
    const int t = threadIdx.x;
    const float v = in[(size_t)blockIdx.x * inStride + t];
    __shared__ float ws[8];

    float s = v;
#pragma unroll
    for (int o = 16; o > 0; o >>= 1) s += __shfl_xor_sync(0xffffffffu, s, o);
    if ((t & 31) == 0) ws[t >> 5] = s;
    __syncthreads();
    float tot = 0.f;
#pragma unroll
    for (int i = 0; i < 8; ++i) tot += ws[i];
    const float mean = tot * (1.f / 256.f);
    __syncthreads();

    const float d = v - mean;
    float s2 = d * d;
#pragma unroll
    for (int o = 16; o > 0; o >>= 1) s2 += __shfl_xor_sync(0xffffffffu, s2, o);
    if ((t & 31) == 0) ws[t >> 5] = s2;
    __syncthreads();
    float tot2 = 0.f;
#pragma unroll
    for (int i = 0; i < 8; ++i) tot2 += ws[i];
    const float var = tot2 * (1.f / 256.f);

    float y = d * rsqrtf(var + EPSLN) * gamma[t] + beta[t];
    if (GELU) y = gelu_exact(y);
    out[(size_t)blockIdx.x * outStride + t] = y;
}

// ---------------- VQ: block per row; argmin over 1024 codes, z_q_st, loss partial, histogram ----------------
__global__ __launch_bounds__(128) void vq_kernel(const float* __restrict__ cb) {
    const int row = blockIdx.x, t = threadIdx.x;
    __shared__ float zs[EED];
    __shared__ float bd[128];
    __shared__ int   bi[128];

    zs[t] = g_ze[row * EED + t];
    __syncthreads();

    float ze2 = 0.f;
    for (int d = 0; d < EED; ++d) ze2 = fmaf(zs[d], zs[d], ze2);

    float best = 3.4e38f;
    int bestk = 0;
    for (int k = t; k < KKC; k += 128) {
        const float* c = cb + (size_t)k * EED;
        float dot = 0.f, c2 = 0.f;
        for (int d = 0; d < EED; ++d) {
            float cv = c[d];
            dot = fmaf(cv, zs[d], dot);
            c2  = fmaf(cv, cv, c2);
        }
        float d2 = (ze2 - 2.f * dot) + c2;   // match ref association
        if (d2 < best) { best = d2; bestk = k; }
    }
    bd[t] = best; bi[t] = bestk;
    __syncthreads();
    for (int o = 64; o > 0; o >>= 1) {
        if (t < o) {
            float ob = bd[t + o]; int oi = bi[t + o];
            if (ob < bd[t] || (ob == bd[t] && oi < bi[t])) { bd[t] = ob; bi[t] = oi; }
        }
        __syncthreads();
    }
    const int widx = bi[0];
    __syncthreads();

    const float zq  = cb[(size_t)widx * EED + t];
    const float zev = zs[t];
    g_zqst[row * EED + t] = zev + (zq - zev);
    const float df = zq - zev;
    bd[t] = df * df;
    __syncthreads();
    for (int o = 64; o > 0; o >>= 1) {
        if (t < o) bd[t] += bd[t + o];
        __syncthreads();
    }
    if (t == 0) {
        g_idx[row] = widx;
        g_lossrow[row] = bd[0];
        atomicAdd(&g_hist[widx], 1.0f);   // exact integer sums: order-independent
    }
}

// ---------------- final 2-wide head: velocity = d2 @ Wd3^T + bd3 ----------------
__global__ __launch_bounds__(128) void head_kernel(
    const float* __restrict__ Wd3, const float* __restrict__ bd3,
    float* __restrict__ out, int out_size)
{
    const int row = blockIdx.x, t = threadIdx.x;
    __shared__ float sred[4];
    const float x = g_d2[row * EED + t];
    for (int c = 0; c < 2; ++c) {
        float p = x * Wd3[c * EED + t];
#pragma unroll
        for (int o = 16; o > 0; o >>= 1) p += __shfl_xor_sync(0xffffffffu, p, o);
        if ((t & 31) == 0) sred[t >> 5] = p;
        __syncthreads();
        if (t == 0) {
            float tot = sred[0] + sred[1] + sred[2] + sred[3];
            int oi = row * 2 + c;
            if (oi < out_size) out[oi] = tot + bd3[c];
        }
        __syncthreads();
    }
}

// ---------------- indices to output (as float) ----------------
__global__ void idx_copy_kernel(float* out, int out_size) {
    int i = blockIdx.x * blockDim.x + threadIdx.x;
    if (i < BB) {
        int oi = 2 * BB + i;  // after velocity (2048*2)
        if (oi < out_size) out[oi] = (float)g_idx[i];
    }
}

// ---------------- scalars: commitment loss + perplexity (deterministic tree reduce) ----------------
__global__ __launch_bounds__(1024) void finalize_kernel(float* out, int out_size) {
    const int t = threadIdx.x;
    __shared__ float sh[1024];

    // perplexity
    float p = g_hist[t] * (1.f / 2048.f);
    sh[t] = p * logf(p + 1e-10f);
    __syncthreads();
    for (int o = 512; o > 0; o >>= 1) {
        if (t < o) sh[t] += sh[t + o];
        __syncthreads();
    }
    const float perp = expf(-sh[0]);
    __syncthreads();

    // commitment loss
    sh[t] = g_lossrow[t] + g_lossrow[t + 1024];
    __syncthreads();
    for (int o = 512; o > 0; o >>= 1) {
        if (t < o) sh[t] += sh[t + o];
        __syncthreads();
    }
    if (t == 0) {
        int li = 2 * BB + BB;       // 6144
        if (li < out_size)     out[li]     = 0.1f * sh[0] / (float)(BB * EED);
        if (li + 1 < out_size) out[li + 1] = perp;
    }
}

// ---------------- launch ----------------
extern "C" void kernel_launch(void* const* d_in, const int* in_sizes, int n_in,
                              void* d_out, int out_size)
{
    const float* x         = (const float*)d_in[0];
    const float* W_in      = (const float*)d_in[1];
    const float* b_in      = (const float*)d_in[2];
    const float* cls_token = (const float*)d_in[3];
    const float* Wqkv      = (const float*)d_in[4];
    const float* bqkv      = (const float*)d_in[5];
    const float* Wo        = (const float*)d_in[6];
    const float* bo        = (const float*)d_in[7];
    const float* W1        = (const float*)d_in[8];
    const float* b1        = (const float*)d_in[9];
    const float* W2        = (const float*)d_in[10];
    const float* b2        = (const float*)d_in[11];
    const float* ln1_g     = (const float*)d_in[12];
    const float* ln1_b     = (const float*)d_in[13];
    const float* ln2_g     = (const float*)d_in[14];
    const float* ln2_b     = (const float*)d_in[15];
    const float* lnf_g     = (const float*)d_in[16];
    const float* lnf_b     = (const float*)d_in[17];
    const float* W_out     = (const float*)d_in[18];
    const float* b_out     = (const float*)d_in[19];
    const float* codebook  = (const float*)d_in[20];
    const float* Wd1       = (const float*)d_in[21];
    const float* bd1       = (const float*)d_in[22];
    const float* lnd_g     = (const float*)d_in[23];
    const float* lnd_b     = (const float*)d_in[24];
    const float* Wd2       = (const float*)d_in[25];
    const float* bd2       = (const float*)d_in[26];
    const float* Wd3       = (const float*)d_in[27];
    const float* bd3       = (const float*)d_in[28];
    float* out = (float*)d_out;

    float *p_h, *p_qkv, *p_o, *p_ff, *p_cls, *p_ze, *p_zqst, *p_d1, *p_d2;
    cudaGetSymbolAddress((void**)&p_h,    g_h);
    cudaGetSymbolAddress((void**)&p_qkv,  g_qkv);
    cudaGetSymbolAddress((void**)&p_o,    g_o);
    cudaGetSymbolAddress((void**)&p_ff,   g_ff);
    cudaGetSymbolAddress((void**)&p_cls,  g_cls);
    cudaGetSymbolAddress((void**)&p_ze,   g_ze);
    cudaGetSymbolAddress((void**)&p_zqst, g_zqst);
    cudaGetSymbolAddress((void**)&p_d1,   g_d1);
    cudaGetSymbolAddress((void**)&p_d2,   g_d2);

    const int MTOK = BB * SS;        // 131072
    const int MALL = BB * TTT;       // 133120

    {
        int n = out_size > KKC ? out_size : KKC;
        zero_kernel<<<(n + 255) / 256, 256>>>(out, out_size);
    }
    pe_init_kernel<<<(SS * DD + 255) / 256, 256>>>();
    cls_fill_kernel<<<(BB * DD + 255) / 256, 256>>>(cls_token);

    // input projection + PE, scattered into h rows (skipping cls rows)
    gemm128<3><<<dim3(MTOK / 128, DD / 128), 256>>>(x, W_in, b_in, nullptr, p_h, MTOK, DD, CC);

    for (int l = 0; l < LLY; ++l) {
        const float* Wqkv_l = Wqkv + (size_t)l * 3 * DD * DD;
        const float* bqkv_l = bqkv + (size_t)l * 3 * DD;
        const float* Wo_l   = Wo   + (size_t)l * DD * DD;
        const float* bo_l   = bo   + (size_t)l * DD;
        const float* W1_l   = W1   + (size_t)l * FFD * DD;
        const float* b1_l   = b1   + (size_t)l * FFD;
        const float* W2_l   = W2   + (size_t)l * DD * FFD;
        const float* b2_l   = b2   + (size_t)l * DD;

        gemm128<0><<<dim3(MALL / 128, (3 * DD) / 128), 256>>>(p_h, Wqkv_l, bqkv_l, nullptr, p_qkv, MALL, 3 * DD, DD);
        attn_kernel<<<BB * HHD, 128>>>();
        gemm128<2><<<dim3(MALL / 128, DD / 128), 256>>>(p_o, Wo_l, bo_l, p_h, p_h, MALL, DD, DD);
        ln_kernel<0><<<MALL, 256>>>(p_h, p_h, ln1_g + l * DD, ln1_b + l * DD, DD, DD);
        gemm128<1><<<dim3(MALL / 128, FFD / 128), 256>>>(p_h, W1_l, b1_l, nullptr, p_ff, MALL, FFD, DD);
        gemm128<2><<<dim3(MALL / 128, DD / 128), 256>>>(p_ff, W2_l, b2_l, p_h, p_h, MALL, DD, FFD);
        ln_kernel<0><<<MALL, 256>>>(p_h, p_h, ln2_g + l * DD, ln2_b + l * DD, DD, DD);
    }

    // cls row LN -> z_e
    ln_kernel<0><<<BB, 256>>>(p_h, p_cls, lnf_g, lnf_b, (size_t)TTT * DD, DD);
    gemm128<0><<<dim3(BB / 128, EED / 128), 256>>>(p_cls, W_out, b_out, nullptr, p_ze, BB, EED, DD);

    // VQ
    vq_kernel<<<BB, 128>>>(codebook);

    // decoder
    gemm128<0><<<dim3(BB / 128, DD / 128), 256>>>(p_zqst, Wd1, bd1, nullptr, p_d1, BB, DD, EED);
    ln_kernel<1><<<BB, 256>>>(p_d1, p_d1, lnd_g, lnd_b, DD, DD);
    gemm128<1><<<dim3(BB / 128, EED / 128), 256>>>(p_d1, Wd2, bd2, nullptr, p_d2, BB, EED, DD);
    head_kernel<<<BB, 128>>>(Wd3, bd3, out, out_size);

    idx_copy_kernel<<<(BB + 255) / 256, 256>>>(out, out_size);
    finalize_kernel<<<1, 1024>>>(out, out_size);
}

// round 4
// speedup vs baseline: 1.1512x; 1.1512x over previous
#include <cuda_runtime.h>
#include <math.h>
#include <stdint.h>

// ---------------- problem constants ----------------
constexpr int BB  = 2048;
constexpr int SS  = 64;
constexpr int CC  = 142;
constexpr int DD  = 256;
constexpr int HHD = 8;    // heads
constexpr int DHH = 32;   // head dim
constexpr int FFD = 512;
constexpr int LLY = 3;
constexpr int EED = 128;  // z_e dim
constexpr int KKC = 1024; // codebook size
constexpr int TTT = 65;   // S + 1
#define EPSLN 1e-5f

// ---------------- scratch (device globals; no allocs allowed) ----------------
__device__ float g_h   [(size_t)BB * TTT * DD];
__device__ float g_qkv [(size_t)BB * TTT * 3 * DD];
__device__ float g_o   [(size_t)BB * TTT * DD];
__device__ float g_ff  [(size_t)BB * TTT * FFD];
__device__ float g_cls [BB * DD];
__device__ float g_ze  [BB * EED];
__device__ float g_zqst[BB * EED];
__device__ float g_d1  [BB * DD];
__device__ float g_d2  [BB * EED];
__device__ float g_lossrow[BB];
__device__ float g_hist[KKC];
__device__ int   g_idx [BB];
__device__ float g_pe  [SS * DD];

// ---------------- helpers ----------------
__device__ __forceinline__ float gelu_exact(float v) {
    return 0.5f * v * (1.f + erff(v * 0.70710678118654752f));
}

__device__ __forceinline__ void split_tf32(float x, float& h, float& l) {
    uint32_t hb; asm("cvt.rna.tf32.f32 %0, %1;" : "=r"(hb) : "f"(x));
    h = __uint_as_float(hb);
    uint32_t lb; asm("cvt.rna.tf32.f32 %0, %1;" : "=r"(lb) : "f"(x - h));
    l = __uint_as_float(lb);
}

__device__ __forceinline__ void mma1688(float* d, const uint32_t* a, const uint32_t* b) {
    asm volatile(
        "mma.sync.aligned.m16n8k8.row.col.f32.tf32.tf32.f32 "
        "{%0,%1,%2,%3}, {%4,%5,%6,%7}, {%8,%9}, {%0,%1,%2,%3};"
        : "+f"(d[0]), "+f"(d[1]), "+f"(d[2]), "+f"(d[3])
        : "r"(a[0]), "r"(a[1]), "r"(a[2]), "r"(a[3]), "r"(b[0]), "r"(b[1]));
}

// ---------------- PE table ----------------
__global__ void pe_init_kernel() {
    int i = blockIdx.x * blockDim.x + threadIdx.x;
    if (i < SS * DD) {
        int s = i >> 8, n = i & 255;
        double div = exp((double)(n & ~1) * (-9.210340371976184 / 256.0));
        double v = (n & 1) ? cos((double)s * div) : sin((double)s * div);
        g_pe[i] = (float)v;
    }
}

__global__ void zero_kernel(float* out, int out_size) {
    int i = blockIdx.x * blockDim.x + threadIdx.x;
    if (i < out_size) out[i] = 0.f;
    if (i < KKC) g_hist[i] = 0.f;
}

__global__ void cls_fill_kernel(const float* __restrict__ cls) {
    int i = blockIdx.x * blockDim.x + threadIdx.x;
    if (i < BB * DD) {
        int b = i >> 8, d = i & 255;
        g_h[(size_t)b * TTT * DD + d] = cls[d];
    }
}

// ---------------- 3xTF32 tensor-core GEMM: C = A[M,K] * W[N,K]^T + bias ----------------
// EPI: 0=bias, 1=bias+gelu, 2=bias+residual, 3=bias+PE scatter (skip cls rows)
// CTA tile 128x128, BK=16, 8 warps (4m x 2n), warp tile 32x64.
template <int EPI>
__global__ __launch_bounds__(256, 2) void gemm_tc(
    const float* __restrict__ A, const float* __restrict__ W,
    const float* __restrict__ bias, const float* __restrict__ resid,
    float* __restrict__ C, int M, int N, int K)
{
    __shared__ float As_hi[16][136];
    __shared__ float As_lo[16][136];
    __shared__ float Bs_hi[16][136];
    __shared__ float Bs_lo[16][136];

    const int tid  = threadIdx.x;
    const int warp = tid >> 5, lane = tid & 31;
    const int g    = lane >> 2;      // 0..7
    const int tg   = lane & 3;       // 0..3
    const int wm   = (warp >> 1) * 32;
    const int wn   = (warp & 1) * 64;
    const int m0   = blockIdx.x * 128, n0 = blockIdx.y * 128;

    float acc[2][8][4];
#pragma unroll
    for (int i = 0; i < 2; ++i)
#pragma unroll
        for (int j = 0; j < 8; ++j)
#pragma unroll
            for (int c = 0; c < 4; ++c) acc[i][j][c] = 0.f;

    // gmem->smem mapping: r = tid>>2 (0..63), k_local = (tid&3) + 4j (j=0..3)
    const int lr = tid >> 2;
    const int lt = tid & 3;

    for (int k0 = 0; k0 < K; k0 += 16) {
#pragma unroll
        for (int half = 0; half < 2; ++half) {
            const int rr = lr + half * 64;
            const float* Ap = A + (size_t)(m0 + rr) * K + k0;
            const float* Wp = W + (size_t)(n0 + rr) * K + k0;
#pragma unroll
            for (int j = 0; j < 4; ++j) {
                const int kl = lt + 4 * j;
                const bool kin = (k0 + kl < K);
                float xa = kin ? Ap[kl] : 0.f;
                float xb = kin ? Wp[kl] : 0.f;
                float h, l;
                split_tf32(xa, h, l);
                As_hi[kl][rr] = h; As_lo[kl][rr] = l;
                split_tf32(xb, h, l);
                Bs_hi[kl][rr] = h; Bs_lo[kl][rr] = l;
            }
        }
        __syncthreads();

#pragma unroll
        for (int kk = 0; kk < 16; kk += 8) {
            uint32_t ah[2][4], al[2][4];
#pragma unroll
            for (int mt = 0; mt < 2; ++mt) {
                const int mr = wm + mt * 16;
                ah[mt][0] = __float_as_uint(As_hi[kk + tg    ][mr + g    ]);
                ah[mt][1] = __float_as_uint(As_hi[kk + tg    ][mr + g + 8]);
                ah[mt][2] = __float_as_uint(As_hi[kk + tg + 4][mr + g    ]);
                ah[mt][3] = __float_as_uint(As_hi[kk + tg + 4][mr + g + 8]);
                al[mt][0] = __float_as_uint(As_lo[kk + tg    ][mr + g    ]);
                al[mt][1] = __float_as_uint(As_lo[kk + tg    ][mr + g + 8]);
                al[mt][2] = __float_as_uint(As_lo[kk + tg + 4][mr + g    ]);
                al[mt][3] = __float_as_uint(As_lo[kk + tg + 4][mr + g + 8]);
            }
#pragma unroll
            for (int nt = 0; nt < 8; ++nt) {
                const int nc = wn + nt * 8;
                uint32_t bh[2], bl[2];
                bh[0] = __float_as_uint(Bs_hi[kk + tg    ][nc + g]);
                bh[1] = __float_as_uint(Bs_hi[kk + tg + 4][nc + g]);
                bl[0] = __float_as_uint(Bs_lo[kk + tg    ][nc + g]);
                bl[1] = __float_as_uint(Bs_lo[kk + tg + 4][nc + g]);
#pragma unroll
                for (int mt = 0; mt < 2; ++mt) {
                    mma1688(acc[mt][nt], ah[mt], bh);   // hi * hi
                    mma1688(acc[mt][nt], ah[mt], bl);   // hi * lo
                    mma1688(acc[mt][nt], al[mt], bh);   // lo * hi
                }
            }
        }
        __syncthreads();
    }

    // epilogue
#pragma unroll
    for (int mt = 0; mt < 2; ++mt) {
#pragma unroll
        for (int nt = 0; nt < 8; ++nt) {
#pragma unroll
            for (int c = 0; c < 4; ++c) {
                const int m = m0 + wm + mt * 16 + g + ((c >> 1) ? 8 : 0);
                const int n = n0 + wn + nt * 8 + 2 * tg + (c & 1);
                float v = acc[mt][nt][c] + bias[n];
                if (EPI == 1) {
                    C[(size_t)m * N + n] = gelu_exact(v);
                } else if (EPI == 2) {
                    v += resid[(size_t)m * N + n];
                    C[(size_t)m * N + n] = v;
                } else if (EPI == 3) {
                    const int bi = m >> 6;
                    const int s  = m & 63;
                    v += g_pe[s * DD + n];
                    C[(size_t)(m + bi + 1) * N + n] = v;
                } else {
                    C[(size_t)m * N + n] = v;
                }
            }
        }
    }
}

// ---------------- attention: one block per (b, head) ----------------
__global__ __launch_bounds__(128) void attn_kernel() {
    const int bh = blockIdx.x;
    const int b = bh >> 3, hd = bh & 7;
    __shared__ float Ks[TTT][DHH + 1];
    __shared__ float Vs[TTT][DHH + 1];
    __shared__ float Ps[TTT][TTT + 1];
    const int tid = threadIdx.x;
    const size_t base = (size_t)b * TTT * 768;

    for (int i = tid; i < TTT * DHH; i += 128) {
        int t = i >> 5, d = i & 31;
        size_t rb = base + (size_t)t * 768 + hd * 32 + d;
        Ks[t][d] = g_qkv[rb + 256];
        Vs[t][d] = g_qkv[rb + 512];
    }
    __syncthreads();

    if (tid < TTT) {
        const int qi = tid;
        float q[DHH];
        const size_t qb = base + (size_t)qi * 768 + hd * 32;
#pragma unroll
        for (int d = 0; d < DHH; ++d) q[d] = g_qkv[qb + d];

        float mx = -1e30f;
        for (int ki = 0; ki < TTT; ++ki) {
            float s = 0.f;
#pragma unroll
            for (int d = 0; d < DHH; ++d) s = fmaf(q[d], Ks[ki][d], s);
            s *= 0.17677669529663687f;
            Ps[qi][ki] = s;
            mx = fmaxf(mx, s);
        }
        float sum = 0.f;
        for (int ki = 0; ki < TTT; ++ki) {
            float e = expf(Ps[qi][ki] - mx);
            Ps[qi][ki] = e;
            sum += e;
        }
        const float inv = 1.f / sum;

        float acc[DHH];
#pragma unroll
        for (int d = 0; d < DHH; ++d) acc[d] = 0.f;
        for (int ki = 0; ki < TTT; ++ki) {
            float p = Ps[qi][ki];
#pragma unroll
            for (int d = 0; d < DHH; ++d) acc[d] = fmaf(p, Vs[ki][d], acc[d]);
        }
        const size_t ob = ((size_t)b * TTT + qi) * DD + hd * 32;
#pragma unroll
        for (int d = 0; d < DHH; ++d) g_o[ob + d] = acc[d] * inv;
    }
}

// ---------------- LayerNorm over last dim (256), optional GELU after ----------------
template <int GELU>
__global__ __launch_bounds__(256) void ln_kernel(
    const float* __restrict__ in, float* __restrict__ out,
    const float* __restrict__ gamma, const float* __restrict__ beta,
    size_t inStride, size_t outStride)
{
    const int t = threadIdx.x;
    const float v = in[(size_t)blockIdx.x * inStride + t];
    __shared__ float ws[8];

    float s = v;
#pragma unroll
    for (int o = 16; o > 0; o >>= 1) s += __shfl_xor_sync(0xffffffffu, s, o);
    if ((t & 31) == 0) ws[t >> 5] = s;
    __syncthreads();
    float tot = 0.f;
#pragma unroll
    for (int i = 0; i < 8; ++i) tot += ws[i];
    const float mean = tot * (1.f / 256.f);
    __syncthreads();

    const float d = v - mean;
    float s2 = d * d;
#pragma unroll
    for (int o = 16; o > 0; o >>= 1) s2 += __shfl_xor_sync(0xffffffffu, s2, o);
    if ((t & 31) == 0) ws[t >> 5] = s2;
    __syncthreads();
    float tot2 = 0.f;
#pragma unroll
    for (int i = 0; i < 8; ++i) tot2 += ws[i];
    const float var = tot2 * (1.f / 256.f);

    float y = d * rsqrtf(var + EPSLN) * gamma[t] + beta[t];
    if (GELU) y = gelu_exact(y);
    out[(size_t)blockIdx.x * outStride + t] = y;
}

// ---------------- VQ ----------------
__global__ __launch_bounds__(128) void vq_kernel(const float* __restrict__ cb) {
    const int row = blockIdx.x, t = threadIdx.x;
    __shared__ float zs[EED];
    __shared__ float bd[128];
    __shared__ int   bi[128];

    zs[t] = g_ze[row * EED + t];
    __syncthreads();

    float ze2 = 0.f;
    for (int d = 0; d < EED; ++d) ze2 = fmaf(zs[d], zs[d], ze2);

    float best = 3.4e38f;
    int bestk = 0;
    for (int k = t; k < KKC; k += 128) {
        const float* c = cb + (size_t)k * EED;
        float dot = 0.f, c2 = 0.f;
        for (int d = 0; d < EED; ++d) {
            float cv = c[d];
            dot = fmaf(cv, zs[d], dot);
            c2  = fmaf(cv, cv, c2);
        }
        float d2 = (ze2 - 2.f * dot) + c2;
        if (d2 < best) { best = d2; bestk = k; }
    }
    bd[t] = best; bi[t] = bestk;
    __syncthreads();
    for (int o = 64; o > 0; o >>= 1) {
        if (t < o) {
            float ob = bd[t + o]; int oi = bi[t + o];
            if (ob < bd[t] || (ob == bd[t] && oi < bi[t])) { bd[t] = ob; bi[t] = oi; }
        }
        __syncthreads();
    }
    const int widx = bi[0];
    __syncthreads();

    const float zq  = cb[(size_t)widx * EED + t];
    const float zev = zs[t];
    g_zqst[row * EED + t] = zev + (zq - zev);
    const float df = zq - zev;
    bd[t] = df * df;
    __syncthreads();
    for (int o = 64; o > 0; o >>= 1) {
        if (t < o) bd[t] += bd[t + o];
        __syncthreads();
    }
    if (t == 0) {
        g_idx[row] = widx;
        g_lossrow[row] = bd[0];
        atomicAdd(&g_hist[widx], 1.0f);
    }
}

// ---------------- final 2-wide head ----------------
__global__ __launch_bounds__(128) void head_kernel(
    const float* __restrict__ Wd3, const float* __restrict__ bd3,
    float* __restrict__ out, int out_size)
{
    const int row = blockIdx.x, t = threadIdx.x;
    __shared__ float sred[4];
    const float x = g_d2[row * EED + t];
    for (int c = 0; c < 2; ++c) {
        float p = x * Wd3[c * EED + t];
#pragma unroll
        for (int o = 16; o > 0; o >>= 1) p += __shfl_xor_sync(0xffffffffu, p, o);
        if ((t & 31) == 0) sred[t >> 5] = p;
        __syncthreads();
        if (t == 0) {
            float tot = sred[0] + sred[1] + sred[2] + sred[3];
            int oi = row * 2 + c;
            if (oi < out_size) out[oi] = tot + bd3[c];
        }
        __syncthreads();
    }
}

__global__ void idx_copy_kernel(float* out, int out_size) {
    int i = blockIdx.x * blockDim.x + threadIdx.x;
    if (i < BB) {
        int oi = 2 * BB + i;
        if (oi < out_size) out[oi] = (float)g_idx[i];
    }
}

__global__ __launch_bounds__(1024) void finalize_kernel(float* out, int out_size) {
    const int t = threadIdx.x;
    __shared__ float sh[1024];

    float p = g_hist[t] * (1.f / 2048.f);
    sh[t] = p * logf(p + 1e-10f);
    __syncthreads();
    for (int o = 512; o > 0; o >>= 1) {
        if (t < o) sh[t] += sh[t + o];
        __syncthreads();
    }
    const float perp = expf(-sh[0]);
    __syncthreads();

    sh[t] = g_lossrow[t] + g_lossrow[t + 1024];
    __syncthreads();
    for (int o = 512; o > 0; o >>= 1) {
        if (t < o) sh[t] += sh[t + o];
        __syncthreads();
    }
    if (t == 0) {
        int li = 2 * BB + BB;
        if (li < out_size)     out[li]     = 0.1f * sh[0] / (float)(BB * EED);
        if (li + 1 < out_size) out[li + 1] = perp;
    }
}

// ---------------- launch ----------------
extern "C" void kernel_launch(void* const* d_in, const int* in_sizes, int n_in,
                              void* d_out, int out_size)
{
    const float* x         = (const float*)d_in[0];
    const float* W_in      = (const float*)d_in[1];
    const float* b_in      = (const float*)d_in[2];
    const float* cls_token = (const float*)d_in[3];
    const float* Wqkv      = (const float*)d_in[4];
    const float* bqkv      = (const float*)d_in[5];
    const float* Wo        = (const float*)d_in[6];
    const float* bo        = (const float*)d_in[7];
    const float* W1        = (const float*)d_in[8];
    const float* b1        = (const float*)d_in[9];
    const float* W2        = (const float*)d_in[10];
    const float* b2        = (const float*)d_in[11];
    const float* ln1_g     = (const float*)d_in[12];
    const float* ln1_b     = (const float*)d_in[13];
    const float* ln2_g     = (const float*)d_in[14];
    const float* ln2_b     = (const float*)d_in[15];
    const float* lnf_g     = (const float*)d_in[16];
    const float* lnf_b     = (const float*)d_in[17];
    const float* W_out     = (const float*)d_in[18];
    const float* b_out     = (const float*)d_in[19];
    const float* codebook  = (const float*)d_in[20];
    const float* Wd1       = (const float*)d_in[21];
    const float* bd1       = (const float*)d_in[22];
    const float* lnd_g     = (const float*)d_in[23];
    const float* lnd_b     = (const float*)d_in[24];
    const float* Wd2       = (const float*)d_in[25];
    const float* bd2       = (const float*)d_in[26];
    const float* Wd3       = (const float*)d_in[27];
    const float* bd3       = (const float*)d_in[28];
    float* out = (float*)d_out;

    float *p_h, *p_qkv, *p_o, *p_ff, *p_cls, *p_ze, *p_zqst, *p_d1, *p_d2;
    cudaGetSymbolAddress((void**)&p_h,    g_h);
    cudaGetSymbolAddress((void**)&p_qkv,  g_qkv);
    cudaGetSymbolAddress((void**)&p_o,    g_o);
    cudaGetSymbolAddress((void**)&p_ff,   g_ff);
    cudaGetSymbolAddress((void**)&p_cls,  g_cls);
    cudaGetSymbolAddress((void**)&p_ze,   g_ze);
    cudaGetSymbolAddress((void**)&p_zqst, g_zqst);
    cudaGetSymbolAddress((void**)&p_d1,   g_d1);
    cudaGetSymbolAddress((void**)&p_d2,   g_d2);

    const int MTOK = BB * SS;        // 131072
    const int MALL = BB * TTT;       // 133120

    {
        int n = out_size > KKC ? out_size : KKC;
        zero_kernel<<<(n + 255) / 256, 256>>>(out, out_size);
    }
    pe_init_kernel<<<(SS * DD + 255) / 256, 256>>>();
    cls_fill_kernel<<<(BB * DD + 255) / 256, 256>>>(cls_token);

    // input projection + PE, scattered into h rows (skipping cls rows)
    gemm_tc<3><<<dim3(MTOK / 128, DD / 128), 256>>>(x, W_in, b_in, nullptr, p_h, MTOK, DD, CC);

    for (int l = 0; l < LLY; ++l) {
        const float* Wqkv_l = Wqkv + (size_t)l * 3 * DD * DD;
        const float* bqkv_l = bqkv + (size_t)l * 3 * DD;
        const float* Wo_l   = Wo   + (size_t)l * DD * DD;
        const float* bo_l   = bo   + (size_t)l * DD;
        const float* W1_l   = W1   + (size_t)l * FFD * DD;
        const float* b1_l   = b1   + (size_t)l * FFD;
        const float* W2_l   = W2   + (size_t)l * DD * FFD;
        const float* b2_l   = b2   + (size_t)l * DD;

        gemm_tc<0><<<dim3(MALL / 128, (3 * DD) / 128), 256>>>(p_h, Wqkv_l, bqkv_l, nullptr, p_qkv, MALL, 3 * DD, DD);
        attn_kernel<<<BB * HHD, 128>>>();
        gemm_tc<2><<<dim3(MALL / 128, DD / 128), 256>>>(p_o, Wo_l, bo_l, p_h, p_h, MALL, DD, DD);
        ln_kernel<0><<<MALL, 256>>>(p_h, p_h, ln1_g + l * DD, ln1_b + l * DD, DD, DD);
        gemm_tc<1><<<dim3(MALL / 128, FFD / 128), 256>>>(p_h, W1_l, b1_l, nullptr, p_ff, MALL, FFD, DD);
        gemm_tc<2><<<dim3(MALL / 128, DD / 128), 256>>>(p_ff, W2_l, b2_l, p_h, p_h, MALL, DD, FFD);
        ln_kernel<0><<<MALL, 256>>>(p_h, p_h, ln2_g + l * DD, ln2_b + l * DD, DD, DD);
    }

    // cls row LN -> z_e
    ln_kernel<0><<<BB, 256>>>(p_h, p_cls, lnf_g, lnf_b, (size_t)TTT * DD, DD);
    gemm_tc<0><<<dim3(BB / 128, EED / 128), 256>>>(p_cls, W_out, b_out, nullptr, p_ze, BB, EED, DD);

    // VQ
    vq_kernel<<<BB, 128>>>(codebook);

    // decoder
    gemm_tc<0><<<dim3(BB / 128, DD / 128), 256>>>(p_zqst, Wd1, bd1, nullptr, p_d1, BB, DD, EED);
    ln_kernel<1><<<BB, 256>>>(p_d1, p_d1, lnd_g, lnd_b, DD, DD);
    gemm_tc<1><<<dim3(BB / 128, EED / 128), 256>>>(p_d1, Wd2, bd2, nullptr, p_d2, BB, EED, DD);
    head_kernel<<<BB, 128>>>(Wd3, bd3, out, out_size);

    idx_copy_kernel<<<(BB + 255) / 256, 256>>>(out, out_size);
    finalize_kernel<<<1, 1024>>>(out, out_size);
}

// round 6
// speedup vs baseline: 1.2973x; 1.1269x over previous
#include <cuda_runtime.h>
#include <math.h>
#include <stdint.h>

// ---------------- problem constants ----------------
constexpr int BB  = 2048;
constexpr int SS  = 64;
constexpr int CC  = 142;
constexpr int DD  = 256;
constexpr int HHD = 8;    // heads
constexpr int DHH = 32;   // head dim
constexpr int FFD = 512;
constexpr int LLY = 3;
constexpr int EED = 128;  // z_e dim
constexpr int KKC = 1024; // codebook size
constexpr int TTT = 65;   // S + 1
#define EPSLN 1e-5f

// ---------------- scratch (device globals; no allocs allowed) ----------------
__device__ float g_h   [(size_t)BB * TTT * DD];
__device__ float g_qkv [(size_t)BB * TTT * 3 * DD];
__device__ float g_o   [(size_t)BB * TTT * DD];
__device__ float g_ff  [(size_t)BB * TTT * FFD];
__device__ float g_cls [BB * DD];
__device__ float g_ze  [BB * EED];
__device__ float g_zqst[BB * EED];
__device__ float g_d1  [BB * DD];
__device__ float g_d2  [BB * EED];
__device__ float g_lossrow[BB];
__device__ float g_hist[KKC];
__device__ int   g_idx [BB];
__device__ float g_pe  [SS * DD];

// ---------------- helpers ----------------
__device__ __forceinline__ float gelu_exact(float v) {
    return 0.5f * v * (1.f + erff(v * 0.70710678118654752f));
}

__device__ __forceinline__ void split2(float x, uint32_t& h, uint32_t& l) {
    uint32_t hb; asm("cvt.rna.tf32.f32 %0, %1;" : "=r"(hb) : "f"(x));
    float hf = __uint_as_float(hb);
    asm("cvt.rna.tf32.f32 %0, %1;" : "=r"(l) : "f"(x - hf));
    h = hb;
}

__device__ __forceinline__ void mma1688(float* d, const uint32_t* a, const uint32_t* b) {
    asm volatile(
        "mma.sync.aligned.m16n8k8.row.col.f32.tf32.tf32.f32 "
        "{%0,%1,%2,%3}, {%4,%5,%6,%7}, {%8,%9}, {%0,%1,%2,%3};"
        : "+f"(d[0]), "+f"(d[1]), "+f"(d[2]), "+f"(d[3])
        : "r"(a[0]), "r"(a[1]), "r"(a[2]), "r"(a[3]), "r"(b[0]), "r"(b[1]));
}

__device__ __forceinline__ void cp_async16(uint32_t dst, const void* src, int src_bytes) {
    asm volatile("cp.async.cg.shared.global [%0], [%1], 16, %2;\n"
                 :: "r"(dst), "l"(src), "r"(src_bytes) : "memory");
}
__device__ __forceinline__ void cp_async_commit() {
    asm volatile("cp.async.commit_group;\n" ::: "memory");
}
__device__ __forceinline__ void cp_async_wait0() {
    asm volatile("cp.async.wait_group 0;\n" ::: "memory");
}

// ---------------- PE table ----------------
__global__ void pe_init_kernel() {
    int i = blockIdx.x * blockDim.x + threadIdx.x;
    if (i < SS * DD) {
        int s = i >> 8, n = i & 255;
        double div = exp((double)(n & ~1) * (-9.210340371976184 / 256.0));
        double v = (n & 1) ? cos((double)s * div) : sin((double)s * div);
        g_pe[i] = (float)v;
    }
}

__global__ void zero_kernel(float* out, int out_size) {
    int i = blockIdx.x * blockDim.x + threadIdx.x;
    if (i < out_size) out[i] = 0.f;
    if (i < KKC) g_hist[i] = 0.f;
}

__global__ void cls_fill_kernel(const float* __restrict__ cls) {
    int i = blockIdx.x * blockDim.x + threadIdx.x;
    if (i < BB * DD) {
        int b = i >> 8, d = i & 255;
        g_h[(size_t)b * TTT * DD + d] = cls[d];
    }
}

// ---------------- 3xTF32 tensor-core GEMM (cp.async double-buffered) ----------------
// C = A[M,K] * W[N,K]^T + bias.  EPI: 0=bias, 1=+gelu, 2=+residual, 3=+PE scatter.
// CTA tile 128x128, BK=16, 8 warps (4m x 2n), warp tile 32x64.
// smem raw fp32, layout [row][k] with row stride 20 floats (conflict-free frag loads,
// 16B-aligned rows for cp.async). Split to tf32 hi/lo at consume time.
template <int EPI>
__global__ __launch_bounds__(256, 2) void gemm_tc(
    const float* __restrict__ A, const float* __restrict__ W,
    const float* __restrict__ bias, const float* __restrict__ resid,
    float* __restrict__ C, int M, int N, int K)
{
    __shared__ float As[2][128][20];
    __shared__ float Bs[2][128][20];

    const int tid  = threadIdx.x;
    const int warp = tid >> 5, lane = tid & 31;
    const int g    = lane >> 2;      // 0..7
    const int tg   = lane & 3;       // 0..3
    const int wm   = (warp >> 1) * 32;
    const int wn   = (warp & 1) * 64;
    const int m0   = blockIdx.x * 128, n0 = blockIdx.y * 128;

    float acc[2][8][4];
#pragma unroll
    for (int i = 0; i < 2; ++i)
#pragma unroll
        for (int j = 0; j < 8; ++j)
#pragma unroll
            for (int c = 0; c < 4; ++c) acc[i][j][c] = 0.f;

    const uint32_t sA = (uint32_t)__cvta_generic_to_shared(&As[0][0][0]);
    const uint32_t sB = (uint32_t)__cvta_generic_to_shared(&Bs[0][0][0]);
    const uint32_t stageBytes = 128 * 20 * 4;

    // fill one stage via cp.async: 512 chunks of 16B per array, 2 per thread per array
    auto fill = [&](int stage, int k0) {
        const uint32_t dA = sA + stage * stageBytes;
        const uint32_t dB = sB + stage * stageBytes;
#pragma unroll
        for (int c = 0; c < 2; ++c) {
            const int chunk = tid + c * 256;
            const int row = chunk >> 2;
            const int kl  = (chunk & 3) * 4;
            const int kg  = k0 + kl;
            int rem = K - kg;
            rem = rem < 0 ? 0 : (rem > 4 ? 4 : rem);
            const int bytes = rem * 4;
            const int ks = bytes ? kg : 0;   // keep src pointer in-bounds when empty
            const uint32_t doff = (uint32_t)(row * 20 + kl) * 4;
            cp_async16(dA + doff, A + (size_t)(m0 + row) * K + ks, bytes);
            cp_async16(dB + doff, W + (size_t)(n0 + row) * K + ks, bytes);
        }
    };

    const int NT = (K + 15) >> 4;

    fill(0, 0);
    cp_async_commit();
    cp_async_wait0();
    __syncthreads();

    for (int t = 0; t < NT; ++t) {
        const int cur = t & 1;
        if (t + 1 < NT) {
            fill((t + 1) & 1, (t + 1) * 16);
            cp_async_commit();
        }

        const float (*Ac)[20] = As[cur];
        const float (*Bc)[20] = Bs[cur];

#pragma unroll
        for (int kk = 0; kk < 16; kk += 8) {
            uint32_t ah[2][4], al[2][4];
#pragma unroll
            for (int mt = 0; mt < 2; ++mt) {
                const int mr = wm + mt * 16;
                split2(Ac[mr + g    ][kk + tg    ], ah[mt][0], al[mt][0]);
                split2(Ac[mr + g + 8][kk + tg    ], ah[mt][1], al[mt][1]);
                split2(Ac[mr + g    ][kk + tg + 4], ah[mt][2], al[mt][2]);
                split2(Ac[mr + g + 8][kk + tg + 4], ah[mt][3], al[mt][3]);
            }
#pragma unroll
            for (int nt = 0; nt < 8; ++nt) {
                const int nc = wn + nt * 8;
                uint32_t bh[2], bl[2];
                split2(Bc[nc + g][kk + tg    ], bh[0], bl[0]);
                split2(Bc[nc + g][kk + tg + 4], bh[1], bl[1]);
#pragma unroll
                for (int mt = 0; mt < 2; ++mt) {
                    mma1688(acc[mt][nt], ah[mt], bh);   // hi * hi
                    mma1688(acc[mt][nt], ah[mt], bl);   // hi * lo
                    mma1688(acc[mt][nt], al[mt], bh);   // lo * hi
                }
            }
        }

        if (t + 1 < NT) cp_async_wait0();
        __syncthreads();
    }

    // epilogue
#pragma unroll
    for (int mt = 0; mt < 2; ++mt) {
#pragma unroll
        for (int nt = 0; nt < 8; ++nt) {
#pragma unroll
            for (int c = 0; c < 4; ++c) {
                const int m = m0 + wm + mt * 16 + g + ((c >> 1) ? 8 : 0);
                const int n = n0 + wn + nt * 8 + 2 * tg + (c & 1);
                float v = acc[mt][nt][c] + bias[n];
                if (EPI == 1) {
                    C[(size_t)m * N + n] = gelu_exact(v);
                } else if (EPI == 2) {
                    v += resid[(size_t)m * N + n];
                    C[(size_t)m * N + n] = v;
                } else if (EPI == 3) {
                    const int bi = m >> 6;
                    const int s  = m & 63;
                    v += g_pe[s * DD + n];
                    C[(size_t)(m + bi + 1) * N + n] = v;
                } else {
                    C[(size_t)m * N + n] = v;
                }
            }
        }
    }
}

// ---------------- attention: one block per (b, head) ----------------
__global__ __launch_bounds__(128) void attn_kernel() {
    const int bh = blockIdx.x;
    const int b = bh >> 3, hd = bh & 7;
    __shared__ float Ks[TTT][DHH + 1];
    __shared__ float Vs[TTT][DHH + 1];
    __shared__ float Ps[TTT][TTT + 1];
    const int tid = threadIdx.x;
    const size_t base = (size_t)b * TTT * 768;

    for (int i = tid; i < TTT * DHH; i += 128) {
        int t = i >> 5, d = i & 31;
        size_t rb = base + (size_t)t * 768 + hd * 32 + d;
        Ks[t][d] = g_qkv[rb + 256];
        Vs[t][d] = g_qkv[rb + 512];
    }
    __syncthreads();

    if (tid < TTT) {
        const int qi = tid;
        float q[DHH];
        const size_t qb = base + (size_t)qi * 768 + hd * 32;
#pragma unroll
        for (int d = 0; d < DHH; ++d) q[d] = g_qkv[qb + d];

        float mx = -1e30f;
        for (int ki = 0; ki < TTT; ++ki) {
            float s = 0.f;
#pragma unroll
            for (int d = 0; d < DHH; ++d) s = fmaf(q[d], Ks[ki][d], s);
            s *= 0.17677669529663687f;
            Ps[qi][ki] = s;
            mx = fmaxf(mx, s);
        }
        float sum = 0.f;
        for (int ki = 0; ki < TTT; ++ki) {
            float e = expf(Ps[qi][ki] - mx);
            Ps[qi][ki] = e;
            sum += e;
        }
        const float inv = 1.f / sum;

        float acc[DHH];
#pragma unroll
        for (int d = 0; d < DHH; ++d) acc[d] = 0.f;
        for (int ki = 0; ki < TTT; ++ki) {
            float p = Ps[qi][ki];
#pragma unroll
            for (int d = 0; d < DHH; ++d) acc[d] = fmaf(p, Vs[ki][d], acc[d]);
        }
        const size_t ob = ((size_t)b * TTT + qi) * DD + hd * 32;
#pragma unroll
        for (int d = 0; d < DHH; ++d) g_o[ob + d] = acc[d] * inv;
    }
}

// ---------------- LayerNorm over last dim (256), optional GELU after ----------------
template <int GELU>
__global__ __launch_bounds__(256) void ln_kernel(
    const float* __restrict__ in, float* __restrict__ out,
    const float* __restrict__ gamma, const float* __restrict__ beta,
    size_t inStride, size_t outStride)
{
    const int t = threadIdx.x;
    const float v = in[(size_t)blockIdx.x * inStride + t];
    __shared__ float ws[8];

    float s = v;
#pragma unroll
    for (int o = 16; o > 0; o >>= 1) s += __shfl_xor_sync(0xffffffffu, s, o);
    if ((t & 31) == 0) ws[t >> 5] = s;
    __syncthreads();
    float tot = 0.f;
#pragma unroll
    for (int i = 0; i < 8; ++i) tot += ws[i];
    const float mean = tot * (1.f / 256.f);
    __syncthreads();

    const float d = v - mean;
    float s2 = d * d;
#pragma unroll
    for (int o = 16; o > 0; o >>= 1) s2 += __shfl_xor_sync(0xffffffffu, s2, o);
    if ((t & 31) == 0) ws[t >> 5] = s2;
    __syncthreads();
    float tot2 = 0.f;
#pragma unroll
    for (int i = 0; i < 8; ++i) tot2 += ws[i];
    const float var = tot2 * (1.f / 256.f);

    float y = d * rsqrtf(var + EPSLN) * gamma[t] + beta[t];
    if (GELU) y = gelu_exact(y);
    out[(size_t)blockIdx.x * outStride + t] = y;
}

// ---------------- VQ ----------------
__global__ __launch_bounds__(128) void vq_kernel(const float* __restrict__ cb) {
    const int row = blockIdx.x, t = threadIdx.x;
    __shared__ float zs[EED];
    __shared__ float bd[128];
    __shared__ int   bi[128];

    zs[t] = g_ze[row * EED + t];
    __syncthreads();

    float ze2 = 0.f;
    for (int d = 0; d < EED; ++d) ze2 = fmaf(zs[d], zs[d], ze2);

    float best = 3.4e38f;
    int bestk = 0;
    for (int k = t; k < KKC; k += 128) {
        const float* c = cb + (size_t)k * EED;
        float dot = 0.f, c2 = 0.f;
        for (int d = 0; d < EED; ++d) {
            float cv = c[d];
            dot = fmaf(cv, zs[d], dot);
            c2  = fmaf(cv, cv, c2);
        }
        float d2 = (ze2 - 2.f * dot) + c2;
        if (d2 < best) { best = d2; bestk = k; }
    }
    bd[t] = best; bi[t] = bestk;
    __syncthreads();
    for (int o = 64; o > 0; o >>= 1) {
        if (t < o) {
            float ob = bd[t + o]; int oi = bi[t + o];
            if (ob < bd[t] || (ob == bd[t] && oi < bi[t])) { bd[t] = ob; bi[t] = oi; }
        }
        __syncthreads();
    }
    const int widx = bi[0];
    __syncthreads();

    const float zq  = cb[(size_t)widx * EED + t];
    const float zev = zs[t];
    g_zqst[row * EED + t] = zev + (zq - zev);
    const float df = zq - zev;
    bd[t] = df * df;
    __syncthreads();
    for (int o = 64; o > 0; o >>= 1) {
        if (t < o) bd[t] += bd[t + o];
        __syncthreads();
    }
    if (t == 0) {
        g_idx[row] = widx;
        g_lossrow[row] = bd[0];
        atomicAdd(&g_hist[widx], 1.0f);
    }
}

// ---------------- final 2-wide head ----------------
__global__ __launch_bounds__(128) void head_kernel(
    const float* __restrict__ Wd3, const float* __restrict__ bd3,
    float* __restrict__ out, int out_size)
{
    const int row = blockIdx.x, t = threadIdx.x;
    __shared__ float sred[4];
    const float x = g_d2[row * EED + t];
    for (int c = 0; c < 2; ++c) {
        float p = x * Wd3[c * EED + t];
#pragma unroll
        for (int o = 16; o > 0; o >>= 1) p += __shfl_xor_sync(0xffffffffu, p, o);
        if ((t & 31) == 0) sred[t >> 5] = p;
        __syncthreads();
        if (t == 0) {
            float tot = sred[0] + sred[1] + sred[2] + sred[3];
            int oi = row * 2 + c;
            if (oi < out_size) out[oi] = tot + bd3[c];
        }
        __syncthreads();
    }
}

__global__ void idx_copy_kernel(float* out, int out_size) {
    int i = blockIdx.x * blockDim.x + threadIdx.x;
    if (i < BB) {
        int oi = 2 * BB + i;
        if (oi < out_size) out[oi] = (float)g_idx[i];
    }
}

__global__ __launch_bounds__(1024) void finalize_kernel(float* out, int out_size) {
    const int t = threadIdx.x;
    __shared__ float sh[1024];

    float p = g_hist[t] * (1.f / 2048.f);
    sh[t] = p * logf(p + 1e-10f);
    __syncthreads();
    for (int o = 512; o > 0; o >>= 1) {
        if (t < o) sh[t] += sh[t + o];
        __syncthreads();
    }
    const float perp = expf(-sh[0]);
    __syncthreads();

    sh[t] = g_lossrow[t] + g_lossrow[t + 1024];
    __syncthreads();
    for (int o = 512; o > 0; o >>= 1) {
        if (t < o) sh[t] += sh[t + o];
        __syncthreads();
    }
    if (t == 0) {
        int li = 2 * BB + BB;
        if (li < out_size)     out[li]     = 0.1f * sh[0] / (float)(BB * EED);
        if (li + 1 < out_size) out[li + 1] = perp;
    }
}

// ---------------- launch ----------------
extern "C" void kernel_launch(void* const* d_in, const int* in_sizes, int n_in,
                              void* d_out, int out_size)
{
    const float* x         = (const float*)d_in[0];
    const float* W_in      = (const float*)d_in[1];
    const float* b_in      = (const float*)d_in[2];
    const float* cls_token = (const float*)d_in[3];
    const float* Wqkv      = (const float*)d_in[4];
    const float* bqkv      = (const float*)d_in[5];
    const float* Wo        = (const float*)d_in[6];
    const float* bo        = (const float*)d_in[7];
    const float* W1        = (const float*)d_in[8];
    const float* b1        = (const float*)d_in[9];
    const float* W2        = (const float*)d_in[10];
    const float* b2        = (const float*)d_in[11];
    const float* ln1_g     = (const float*)d_in[12];
    const float* ln1_b     = (const float*)d_in[13];
    const float* ln2_g     = (const float*)d_in[14];
    const float* ln2_b     = (const float*)d_in[15];
    const float* lnf_g     = (const float*)d_in[16];
    const float* lnf_b     = (const float*)d_in[17];
    const float* W_out     = (const float*)d_in[18];
    const float* b_out     = (const float*)d_in[19];
    const float* codebook  = (const float*)d_in[20];
    const float* Wd1       = (const float*)d_in[21];
    const float* bd1       = (const float*)d_in[22];
    const float* lnd_g     = (const float*)d_in[23];
    const float* lnd_b     = (const float*)d_in[24];
    const float* Wd2       = (const float*)d_in[25];
    const float* bd2       = (const float*)d_in[26];
    const float* Wd3       = (const float*)d_in[27];
    const float* bd3       = (const float*)d_in[28];
    float* out = (float*)d_out;

    float *p_h, *p_qkv, *p_o, *p_ff, *p_cls, *p_ze, *p_zqst, *p_d1, *p_d2;
    cudaGetSymbolAddress((void**)&p_h,    g_h);
    cudaGetSymbolAddress((void**)&p_qkv,  g_qkv);
    cudaGetSymbolAddress((void**)&p_o,    g_o);
    cudaGetSymbolAddress((void**)&p_ff,   g_ff);
    cudaGetSymbolAddress((void**)&p_cls,  g_cls);
    cudaGetSymbolAddress((void**)&p_ze,   g_ze);
    cudaGetSymbolAddress((void**)&p_zqst, g_zqst);
    cudaGetSymbolAddress((void**)&p_d1,   g_d1);
    cudaGetSymbolAddress((void**)&p_d2,   g_d2);

    const int MTOK = BB * SS;        // 131072
    const int MALL = BB * TTT;       // 133120

    {
        int n = out_size > KKC ? out_size : KKC;
        zero_kernel<<<(n + 255) / 256, 256>>>(out, out_size);
    }
    pe_init_kernel<<<(SS * DD + 255) / 256, 256>>>();
    cls_fill_kernel<<<(BB * DD + 255) / 256, 256>>>(cls_token);

    // input projection + PE, scattered into h rows (skipping cls rows)
    gemm_tc<3><<<dim3(MTOK / 128, DD / 128), 256>>>(x, W_in, b_in, nullptr, p_h, MTOK, DD, CC);

    for (int l = 0; l < LLY; ++l) {
        const float* Wqkv_l = Wqkv + (size_t)l * 3 * DD * DD;
        const float* bqkv_l = bqkv + (size_t)l * 3 * DD;
        const float* Wo_l   = Wo   + (size_t)l * DD * DD;
        const float* bo_l   = bo   + (size_t)l * DD;
        const float* W1_l   = W1   + (size_t)l * FFD * DD;
        const float* b1_l   = b1   + (size_t)l * FFD;
        const float* W2_l   = W2   + (size_t)l * DD * FFD;
        const float* b2_l   = b2   + (size_t)l * DD;

        gemm_tc<0><<<dim3(MALL / 128, (3 * DD) / 128), 256>>>(p_h, Wqkv_l, bqkv_l, nullptr, p_qkv, MALL, 3 * DD, DD);
        attn_kernel<<<BB * HHD, 128>>>();
        gemm_tc<2><<<dim3(MALL / 128, DD / 128), 256>>>(p_o, Wo_l, bo_l, p_h, p_h, MALL, DD, DD);
        ln_kernel<0><<<MALL, 256>>>(p_h, p_h, ln1_g + l * DD, ln1_b + l * DD, DD, DD);
        gemm_tc<1><<<dim3(MALL / 128, FFD / 128), 256>>>(p_h, W1_l, b1_l, nullptr, p_ff, MALL, FFD, DD);
        gemm_tc<2><<<dim3(MALL / 128, DD / 128), 256>>>(p_ff, W2_l, b2_l, p_h, p_h, MALL, DD, FFD);
        ln_kernel<0><<<MALL, 256>>>(p_h, p_h, ln2_g + l * DD, ln2_b + l * DD, DD, DD);
    }

    // cls row LN -> z_e
    ln_kernel<0><<<BB, 256>>>(p_h, p_cls, lnf_g, lnf_b, (size_t)TTT * DD, DD);
    gemm_tc<0><<<dim3(BB / 128, EED / 128), 256>>>(p_cls, W_out, b_out, nullptr, p_ze, BB, EED, DD);

    // VQ
    vq_kernel<<<BB, 128>>>(codebook);

    // decoder
    gemm_tc<0><<<dim3(BB / 128, DD / 128), 256>>>(p_zqst, Wd1, bd1, nullptr, p_d1, BB, DD, EED);
    ln_kernel<1><<<BB, 256>>>(p_d1, p_d1, lnd_g, lnd_b, DD, DD);
    gemm_tc<1><<<dim3(BB / 128, EED / 128), 256>>>(p_d1, Wd2, bd2, nullptr, p_d2, BB, EED, DD);
    head_kernel<<<BB, 128>>>(Wd3, bd3, out, out_size);

    idx_copy_kernel<<<(BB + 255) / 256, 256>>>(out, out_size);
    finalize_kernel<<<1, 1024>>>(out, out_size);
}

// round 7
// speedup vs baseline: 1.3342x; 1.0284x over previous
#include <cuda_runtime.h>
#include <math.h>
#include <stdint.h>

// ---------------- problem constants ----------------
constexpr int BB  = 2048;
constexpr int SS  = 64;
constexpr int CC  = 142;
constexpr int CCP = 144;  // padded K for input projection (16-float multiple)
constexpr int DD  = 256;
constexpr int HHD = 8;
constexpr int DHH = 32;
constexpr int FFD = 512;
constexpr int LLY = 3;
constexpr int EED = 128;
constexpr int KKC = 1024;
constexpr int TTT = 65;
#define EPSLN 1e-5f

// ---------------- scratch (device globals; no allocs allowed) ----------------
__device__ float g_h   [(size_t)BB * TTT * DD];
__device__ float g_qkv [(size_t)BB * TTT * 3 * DD];
__device__ float g_o   [(size_t)BB * TTT * DD];
__device__ float g_ff  [(size_t)BB * TTT * FFD];
__device__ float g_cls [BB * DD];
__device__ float g_ze  [BB * EED];
__device__ float g_zqst[BB * EED];
__device__ float g_d1  [BB * DD];
__device__ float g_d2  [BB * EED];
__device__ float g_lossrow[BB];
__device__ float g_hist[KKC];
__device__ int   g_idx [BB];
__device__ float g_pe  [SS * DD];

// padded input + pre-split tf32 weight planes
__device__ float g_xpad [(size_t)BB * SS * CCP];
__device__ float g_wi_h [DD * CCP];
__device__ float g_wi_l [DD * CCP];
__device__ float g_wq_h [LLY * 3 * DD * DD];
__device__ float g_wq_l [LLY * 3 * DD * DD];
__device__ float g_wo_h [LLY * DD * DD];
__device__ float g_wo_l [LLY * DD * DD];
__device__ float g_w1_h [LLY * FFD * DD];
__device__ float g_w1_l [LLY * FFD * DD];
__device__ float g_w2_h [LLY * DD * FFD];
__device__ float g_w2_l [LLY * DD * FFD];
__device__ float g_wout_h [EED * DD];
__device__ float g_wout_l [EED * DD];
__device__ float g_wd1_h [DD * EED];
__device__ float g_wd1_l [DD * EED];
__device__ float g_wd2_h [EED * DD];
__device__ float g_wd2_l [EED * DD];

// ---------------- helpers ----------------
__device__ __forceinline__ float gelu_exact(float v) {
    return 0.5f * v * (1.f + erff(v * 0.70710678118654752f));
}

__device__ __forceinline__ void split2(float x, uint32_t& h, uint32_t& l) {
    uint32_t hb; asm("cvt.rna.tf32.f32 %0, %1;" : "=r"(hb) : "f"(x));
    float hf = __uint_as_float(hb);
    asm("cvt.rna.tf32.f32 %0, %1;" : "=r"(l) : "f"(x - hf));
    h = hb;
}

__device__ __forceinline__ void mma1688(float* d, const uint32_t* a, const uint32_t* b) {
    asm volatile(
        "mma.sync.aligned.m16n8k8.row.col.f32.tf32.tf32.f32 "
        "{%0,%1,%2,%3}, {%4,%5,%6,%7}, {%8,%9}, {%0,%1,%2,%3};"
        : "+f"(d[0]), "+f"(d[1]), "+f"(d[2]), "+f"(d[3])
        : "r"(a[0]), "r"(a[1]), "r"(a[2]), "r"(a[3]), "r"(b[0]), "r"(b[1]));
}

__device__ __forceinline__ void cp16(uint32_t dst, const void* src) {
    asm volatile("cp.async.cg.shared.global [%0], [%1], 16;\n"
                 :: "r"(dst), "l"(src) : "memory");
}
__device__ __forceinline__ void cp_async_commit() {
    asm volatile("cp.async.commit_group;\n" ::: "memory");
}
__device__ __forceinline__ void cp_async_wait0() {
    asm volatile("cp.async.wait_group 0;\n" ::: "memory");
}

// ---------------- prep kernels ----------------
__global__ void pad_x_kernel(const float* __restrict__ x) {
    int i = blockIdx.x * blockDim.x + threadIdx.x;
    if (i < BB * SS * CCP) {
        int r = i / CCP, c = i - r * CCP;
        g_xpad[i] = (c < CC) ? x[(size_t)r * CC + c] : 0.f;
    }
}

// split weight (N x K raw) into hi/lo planes (N x Kp), zero-padded
__global__ void splitw_kernel(const float* __restrict__ in,
                              float* __restrict__ oh, float* __restrict__ ol,
                              int N, int K, int Kp) {
    int i = blockIdx.x * blockDim.x + threadIdx.x;
    if (i < N * Kp) {
        int r = i / Kp, c = i - r * Kp;
        float v = (c < K) ? in[(size_t)r * K + c] : 0.f;
        uint32_t h, l; split2(v, h, l);
        oh[i] = __uint_as_float(h);
        ol[i] = __uint_as_float(l);
    }
}

// ---------------- misc init ----------------
__global__ void pe_init_kernel() {
    int i = blockIdx.x * blockDim.x + threadIdx.x;
    if (i < SS * DD) {
        int s = i >> 8, n = i & 255;
        double div = exp((double)(n & ~1) * (-9.210340371976184 / 256.0));
        double v = (n & 1) ? cos((double)s * div) : sin((double)s * div);
        g_pe[i] = (float)v;
    }
}

__global__ void zero_kernel(float* out, int out_size) {
    int i = blockIdx.x * blockDim.x + threadIdx.x;
    if (i < out_size) out[i] = 0.f;
    if (i < KKC) g_hist[i] = 0.f;
}

__global__ void cls_fill_kernel(const float* __restrict__ cls) {
    int i = blockIdx.x * blockDim.x + threadIdx.x;
    if (i < BB * DD) {
        int b = i >> 8, d = i & 255;
        g_h[(size_t)b * TTT * DD + d] = cls[d];
    }
}

// ---------------- 3xTF32 tensor-core GEMM, pre-split B planes ----------------
// C = A[M,lda] * B[N,ldb]^T + bias (B given as tf32 hi/lo planes).
// EPI: 0=bias, 1=+gelu, 2=+residual, 3=+PE scatter (skip cls rows).
// CTA tile 128x128, BK=16, 8 warps (4m x 2n). Kp (=ldb) multiple of 16; pads are zero.
// Dynamic smem: A raw 2 stages + Bh 2 stages + Bl 2 stages, each 128x20 floats.
template <int EPI>
__global__ __launch_bounds__(256, 2) void gemm_tc(
    const float* __restrict__ A, const float* __restrict__ Bh, const float* __restrict__ Bl,
    const float* __restrict__ bias, const float* __restrict__ resid,
    float* __restrict__ C, int M, int N, int Kp, int lda)
{
    extern __shared__ float dsm[];   // [6][128][20] : A0,A1,Bh0,Bh1,Bl0,Bl1

    const int tid  = threadIdx.x;
    const int warp = tid >> 5, lane = tid & 31;
    const int g    = lane >> 2;
    const int tg   = lane & 3;
    const int wm   = (warp >> 1) * 32;
    const int wn   = (warp & 1) * 64;
    const int m0   = blockIdx.x * 128, n0 = blockIdx.y * 128;
    const int ldb  = Kp;

    float acc[2][8][4];
#pragma unroll
    for (int i = 0; i < 2; ++i)
#pragma unroll
        for (int j = 0; j < 8; ++j)
#pragma unroll
            for (int c = 0; c < 4; ++c) acc[i][j][c] = 0.f;

    const uint32_t sbase = (uint32_t)__cvta_generic_to_shared(dsm);
    const uint32_t stageB = 128 * 20 * 4;    // 10240 bytes per stage-plane

    auto fill = [&](int stage, int k0) {
        const uint32_t dA  = sbase + stage * stageB;
        const uint32_t dBh = sbase + (2 + stage) * stageB;
        const uint32_t dBl = sbase + (4 + stage) * stageB;
#pragma unroll
        for (int c = 0; c < 2; ++c) {
            const int chunk = tid + c * 256;
            const int row = chunk >> 2;
            const int kl  = (chunk & 3) * 4;
            const uint32_t doff = (uint32_t)(row * 20 + kl) * 4;
            const int kg = k0 + kl;
            cp16(dA  + doff, A  + (size_t)(m0 + row) * lda + kg);
            cp16(dBh + doff, Bh + (size_t)(n0 + row) * ldb + kg);
            cp16(dBl + doff, Bl + (size_t)(n0 + row) * ldb + kg);
        }
    };

    const int NT = Kp >> 4;

    fill(0, 0);
    cp_async_commit();
    cp_async_wait0();
    __syncthreads();

    for (int t = 0; t < NT; ++t) {
        const int cur = t & 1;
        if (t + 1 < NT) {
            fill((t + 1) & 1, (t + 1) * 16);
            cp_async_commit();
        }

        const float* Ac  = dsm + cur * 2560;
        const float* Bhc = dsm + (2 + cur) * 2560;
        const float* Blc = dsm + (4 + cur) * 2560;

#pragma unroll
        for (int kk = 0; kk < 16; kk += 8) {
            uint32_t ah[2][4], al[2][4];
#pragma unroll
            for (int mt = 0; mt < 2; ++mt) {
                const int mr = wm + mt * 16;
                split2(Ac[(mr + g    ) * 20 + kk + tg    ], ah[mt][0], al[mt][0]);
                split2(Ac[(mr + g + 8) * 20 + kk + tg    ], ah[mt][1], al[mt][1]);
                split2(Ac[(mr + g    ) * 20 + kk + tg + 4], ah[mt][2], al[mt][2]);
                split2(Ac[(mr + g + 8) * 20 + kk + tg + 4], ah[mt][3], al[mt][3]);
            }
#pragma unroll
            for (int nt = 0; nt < 8; ++nt) {
                const int nc = wn + nt * 8;
                uint32_t bh[2], bl[2];
                bh[0] = __float_as_uint(Bhc[(nc + g) * 20 + kk + tg    ]);
                bh[1] = __float_as_uint(Bhc[(nc + g) * 20 + kk + tg + 4]);
                bl[0] = __float_as_uint(Blc[(nc + g) * 20 + kk + tg    ]);
                bl[1] = __float_as_uint(Blc[(nc + g) * 20 + kk + tg + 4]);
#pragma unroll
                for (int mt = 0; mt < 2; ++mt) {
                    mma1688(acc[mt][nt], ah[mt], bh);   // hi * hi
                    mma1688(acc[mt][nt], ah[mt], bl);   // hi * lo
                    mma1688(acc[mt][nt], al[mt], bh);   // lo * hi
                }
            }
        }

        if (t + 1 < NT) cp_async_wait0();
        __syncthreads();
    }

    // epilogue
#pragma unroll
    for (int mt = 0; mt < 2; ++mt) {
#pragma unroll
        for (int nt = 0; nt < 8; ++nt) {
#pragma unroll
            for (int c = 0; c < 4; ++c) {
                const int m = m0 + wm + mt * 16 + g + ((c >> 1) ? 8 : 0);
                const int n = n0 + wn + nt * 8 + 2 * tg + (c & 1);
                float v = acc[mt][nt][c] + bias[n];
                if (EPI == 1) {
                    C[(size_t)m * N + n] = gelu_exact(v);
                } else if (EPI == 2) {
                    v += resid[(size_t)m * N + n];
                    C[(size_t)m * N + n] = v;
                } else if (EPI == 3) {
                    const int bi = m >> 6;
                    const int s  = m & 63;
                    v += g_pe[s * DD + n];
                    C[(size_t)(m + bi + 1) * N + n] = v;
                } else {
                    C[(size_t)m * N + n] = v;
                }
            }
        }
    }
}

// ---------------- attention: one block per (b, head) ----------------
__global__ __launch_bounds__(128) void attn_kernel() {
    const int bh = blockIdx.x;
    const int b = bh >> 3, hd = bh & 7;
    __shared__ float Ks[TTT][DHH + 1];
    __shared__ float Vs[TTT][DHH + 1];
    __shared__ float Ps[TTT][TTT + 1];
    const int tid = threadIdx.x;
    const size_t base = (size_t)b * TTT * 768;

    for (int i = tid; i < TTT * DHH; i += 128) {
        int t = i >> 5, d = i & 31;
        size_t rb = base + (size_t)t * 768 + hd * 32 + d;
        Ks[t][d] = g_qkv[rb + 256];
        Vs[t][d] = g_qkv[rb + 512];
    }
    __syncthreads();

    if (tid < TTT) {
        const int qi = tid;
        float q[DHH];
        const size_t qb = base + (size_t)qi * 768 + hd * 32;
#pragma unroll
        for (int d = 0; d < DHH; ++d) q[d] = g_qkv[qb + d];

        float mx = -1e30f;
        for (int ki = 0; ki < TTT; ++ki) {
            float s = 0.f;
#pragma unroll
            for (int d = 0; d < DHH; ++d) s = fmaf(q[d], Ks[ki][d], s);
            s *= 0.17677669529663687f;
            Ps[qi][ki] = s;
            mx = fmaxf(mx, s);
        }
        float sum = 0.f;
        for (int ki = 0; ki < TTT; ++ki) {
            float e = expf(Ps[qi][ki] - mx);
            Ps[qi][ki] = e;
            sum += e;
        }
        const float inv = 1.f / sum;

        float acc[DHH];
#pragma unroll
        for (int d = 0; d < DHH; ++d) acc[d] = 0.f;
        for (int ki = 0; ki < TTT; ++ki) {
            float p = Ps[qi][ki];
#pragma unroll
            for (int d = 0; d < DHH; ++d) acc[d] = fmaf(p, Vs[ki][d], acc[d]);
        }
        const size_t ob = ((size_t)b * TTT + qi) * DD + hd * 32;
#pragma unroll
        for (int d = 0; d < DHH; ++d) g_o[ob + d] = acc[d] * inv;
    }
}

// ---------------- LayerNorm over last dim (256), optional GELU after ----------------
template <int GELU>
__global__ __launch_bounds__(256) void ln_kernel(
    const float* __restrict__ in, float* __restrict__ out,
    const float* __restrict__ gamma, const float* __restrict__ beta,
    size_t inStride, size_t outStride)
{
    const int t = threadIdx.x;
    const float v = in[(size_t)blockIdx.x * inStride + t];
    __shared__ float ws[8];

    float s = v;
#pragma unroll
    for (int o = 16; o > 0; o >>= 1) s += __shfl_xor_sync(0xffffffffu, s, o);
    if ((t & 31) == 0) ws[t >> 5] = s;
    __syncthreads();
    float tot = 0.f;
#pragma unroll
    for (int i = 0; i < 8; ++i) tot += ws[i];
    const float mean = tot * (1.f / 256.f);
    __syncthreads();

    const float d = v - mean;
    float s2 = d * d;
#pragma unroll
    for (int o = 16; o > 0; o >>= 1) s2 += __shfl_xor_sync(0xffffffffu, s2, o);
    if ((t & 31) == 0) ws[t >> 5] = s2;
    __syncthreads();
    float tot2 = 0.f;
#pragma unroll
    for (int i = 0; i < 8; ++i) tot2 += ws[i];
    const float var = tot2 * (1.f / 256.f);

    float y = d * rsqrtf(var + EPSLN) * gamma[t] + beta[t];
    if (GELU) y = gelu_exact(y);
    out[(size_t)blockIdx.x * outStride + t] = y;
}

// ---------------- VQ ----------------
__global__ __launch_bounds__(128) void vq_kernel(const float* __restrict__ cb) {
    const int row = blockIdx.x, t = threadIdx.x;
    __shared__ float zs[EED];
    __shared__ float bd[128];
    __shared__ int   bi[128];

    zs[t] = g_ze[row * EED + t];
    __syncthreads();

    float ze2 = 0.f;
    for (int d = 0; d < EED; ++d) ze2 = fmaf(zs[d], zs[d], ze2);

    float best = 3.4e38f;
    int bestk = 0;
    for (int k = t; k < KKC; k += 128) {
        const float* c = cb + (size_t)k * EED;
        float dot = 0.f, c2 = 0.f;
        for (int d = 0; d < EED; ++d) {
            float cv = c[d];
            dot = fmaf(cv, zs[d], dot);
            c2  = fmaf(cv, cv, c2);
        }
        float d2 = (ze2 - 2.f * dot) + c2;
        if (d2 < best) { best = d2; bestk = k; }
    }
    bd[t] = best; bi[t] = bestk;
    __syncthreads();
    for (int o = 64; o > 0; o >>= 1) {
        if (t < o) {
            float ob = bd[t + o]; int oi = bi[t + o];
            if (ob < bd[t] || (ob == bd[t] && oi < bi[t])) { bd[t] = ob; bi[t] = oi; }
        }
        __syncthreads();
    }
    const int widx = bi[0];
    __syncthreads();

    const float zq  = cb[(size_t)widx * EED + t];
    const float zev = zs[t];
    g_zqst[row * EED + t] = zev + (zq - zev);
    const float df = zq - zev;
    bd[t] = df * df;
    __syncthreads();
    for (int o = 64; o > 0; o >>= 1) {
        if (t < o) bd[t] += bd[t + o];
        __syncthreads();
    }
    if (t == 0) {
        g_idx[row] = widx;
        g_lossrow[row] = bd[0];
        atomicAdd(&g_hist[widx], 1.0f);
    }
}

// ---------------- final 2-wide head ----------------
__global__ __launch_bounds__(128) void head_kernel(
    const float* __restrict__ Wd3, const float* __restrict__ bd3,
    float* __restrict__ out, int out_size)
{
    const int row = blockIdx.x, t = threadIdx.x;
    __shared__ float sred[4];
    const float x = g_d2[row * EED + t];
    for (int c = 0; c < 2; ++c) {
        float p = x * Wd3[c * EED + t];
#pragma unroll
        for (int o = 16; o > 0; o >>= 1) p += __shfl_xor_sync(0xffffffffu, p, o);
        if ((t & 31) == 0) sred[t >> 5] = p;
        __syncthreads();
        if (t == 0) {
            float tot = sred[0] + sred[1] + sred[2] + sred[3];
            int oi = row * 2 + c;
            if (oi < out_size) out[oi] = tot + bd3[c];
        }
        __syncthreads();
    }
}

__global__ void idx_copy_kernel(float* out, int out_size) {
    int i = blockIdx.x * blockDim.x + threadIdx.x;
    if (i < BB) {
        int oi = 2 * BB + i;
        if (oi < out_size) out[oi] = (float)g_idx[i];
    }
}

__global__ __launch_bounds__(1024) void finalize_kernel(float* out, int out_size) {
    const int t = threadIdx.x;
    __shared__ float sh[1024];

    float p = g_hist[t] * (1.f / 2048.f);
    sh[t] = p * logf(p + 1e-10f);
    __syncthreads();
    for (int o = 512; o > 0; o >>= 1) {
        if (t < o) sh[t] += sh[t + o];
        __syncthreads();
    }
    const float perp = expf(-sh[0]);
    __syncthreads();

    sh[t] = g_lossrow[t] + g_lossrow[t + 1024];
    __syncthreads();
    for (int o = 512; o > 0; o >>= 1) {
        if (t < o) sh[t] += sh[t + o];
        __syncthreads();
    }
    if (t == 0) {
        int li = 2 * BB + BB;
        if (li < out_size)     out[li]     = 0.1f * sh[0] / (float)(BB * EED);
        if (li + 1 < out_size) out[li + 1] = perp;
    }
}

// ---------------- launch ----------------
extern "C" void kernel_launch(void* const* d_in, const int* in_sizes, int n_in,
                              void* d_out, int out_size)
{
    const float* x         = (const float*)d_in[0];
    const float* W_in      = (const float*)d_in[1];
    const float* b_in      = (const float*)d_in[2];
    const float* cls_token = (const float*)d_in[3];
    const float* Wqkv      = (const float*)d_in[4];
    const float* bqkv      = (const float*)d_in[5];
    const float* Wo        = (const float*)d_in[6];
    const float* bo        = (const float*)d_in[7];
    const float* W1        = (const float*)d_in[8];
    const float* b1        = (const float*)d_in[9];
    const float* W2        = (const float*)d_in[10];
    const float* b2        = (const float*)d_in[11];
    const float* ln1_g     = (const float*)d_in[12];
    const float* ln1_b     = (const float*)d_in[13];
    const float* ln2_g     = (const float*)d_in[14];
    const float* ln2_b     = (const float*)d_in[15];
    const float* lnf_g     = (const float*)d_in[16];
    const float* lnf_b     = (const float*)d_in[17];
    const float* W_out     = (const float*)d_in[18];
    const float* b_out     = (const float*)d_in[19];
    const float* codebook  = (const float*)d_in[20];
    const float* Wd1       = (const float*)d_in[21];
    const float* bd1       = (const float*)d_in[22];
    const float* lnd_g     = (const float*)d_in[23];
    const float* lnd_b     = (const float*)d_in[24];
    const float* Wd2       = (const float*)d_in[25];
    const float* bd2       = (const float*)d_in[26];
    const float* Wd3       = (const float*)d_in[27];
    const float* bd3       = (const float*)d_in[28];
    float* out = (float*)d_out;

    float *p_h, *p_qkv, *p_o, *p_ff, *p_cls, *p_ze, *p_zqst, *p_d1, *p_d2, *p_xpad;
    float *p_wi_h, *p_wi_l, *p_wq_h, *p_wq_l, *p_wo_h, *p_wo_l;
    float *p_w1_h, *p_w1_l, *p_w2_h, *p_w2_l;
    float *p_wout_h, *p_wout_l, *p_wd1_h, *p_wd1_l, *p_wd2_h, *p_wd2_l;
    cudaGetSymbolAddress((void**)&p_h,    g_h);
    cudaGetSymbolAddress((void**)&p_qkv,  g_qkv);
    cudaGetSymbolAddress((void**)&p_o,    g_o);
    cudaGetSymbolAddress((void**)&p_ff,   g_ff);
    cudaGetSymbolAddress((void**)&p_cls,  g_cls);
    cudaGetSymbolAddress((void**)&p_ze,   g_ze);
    cudaGetSymbolAddress((void**)&p_zqst, g_zqst);
    cudaGetSymbolAddress((void**)&p_d1,   g_d1);
    cudaGetSymbolAddress((void**)&p_d2,   g_d2);
    cudaGetSymbolAddress((void**)&p_xpad, g_xpad);
    cudaGetSymbolAddress((void**)&p_wi_h, g_wi_h);
    cudaGetSymbolAddress((void**)&p_wi_l, g_wi_l);
    cudaGetSymbolAddress((void**)&p_wq_h, g_wq_h);
    cudaGetSymbolAddress((void**)&p_wq_l, g_wq_l);
    cudaGetSymbolAddress((void**)&p_wo_h, g_wo_h);
    cudaGetSymbolAddress((void**)&p_wo_l, g_wo_l);
    cudaGetSymbolAddress((void**)&p_w1_h, g_w1_h);
    cudaGetSymbolAddress((void**)&p_w1_l, g_w1_l);
    cudaGetSymbolAddress((void**)&p_w2_h, g_w2_h);
    cudaGetSymbolAddress((void**)&p_w2_l, g_w2_l);
    cudaGetSymbolAddress((void**)&p_wout_h, g_wout_h);
    cudaGetSymbolAddress((void**)&p_wout_l, g_wout_l);
    cudaGetSymbolAddress((void**)&p_wd1_h, g_wd1_h);
    cudaGetSymbolAddress((void**)&p_wd1_l, g_wd1_l);
    cudaGetSymbolAddress((void**)&p_wd2_h, g_wd2_h);
    cudaGetSymbolAddress((void**)&p_wd2_l, g_wd2_l);

    const int MTOK = BB * SS;        // 131072
    const int MALL = BB * TTT;       // 133120
    const int SMEM = 6 * 128 * 20 * 4;  // 61440 bytes dynamic

    cudaFuncSetAttribute(gemm_tc<0>, cudaFuncAttributeMaxDynamicSharedMemorySize, SMEM);
    cudaFuncSetAttribute(gemm_tc<1>, cudaFuncAttributeMaxDynamicSharedMemorySize, SMEM);
    cudaFuncSetAttribute(gemm_tc<2>, cudaFuncAttributeMaxDynamicSharedMemorySize, SMEM);
    cudaFuncSetAttribute(gemm_tc<3>, cudaFuncAttributeMaxDynamicSharedMemorySize, SMEM);

    {
        int n = out_size > KKC ? out_size : KKC;
        zero_kernel<<<(n + 255) / 256, 256>>>(out, out_size);
    }
    pe_init_kernel<<<(SS * DD + 255) / 256, 256>>>();
    cls_fill_kernel<<<(BB * DD + 255) / 256, 256>>>(cls_token);

    // ---- prep: pad x, split all weights into tf32 hi/lo planes ----
    pad_x_kernel<<<(BB * SS * CCP + 255) / 256, 256>>>(x);
    auto splitw = [&](const float* in, float* oh, float* ol, int N, int K, int Kp) {
        splitw_kernel<<<(N * Kp + 255) / 256, 256>>>(in, oh, ol, N, K, Kp);
    };
    splitw(W_in,  p_wi_h,  p_wi_l,  DD, CC, CCP);
    splitw(Wqkv,  p_wq_h,  p_wq_l,  LLY * 3 * DD, DD, DD);
    splitw(Wo,    p_wo_h,  p_wo_l,  LLY * DD, DD, DD);
    splitw(W1,    p_w1_h,  p_w1_l,  LLY * FFD, DD, DD);
    splitw(W2,    p_w2_h,  p_w2_l,  LLY * DD, FFD, FFD);
    splitw(W_out, p_wout_h, p_wout_l, EED, DD, DD);
    splitw(Wd1,   p_wd1_h, p_wd1_l, DD, EED, EED);
    splitw(Wd2,   p_wd2_h, p_wd2_l, EED, DD, DD);

    // ---- input projection + PE, scattered into h rows (skipping cls rows) ----
    gemm_tc<3><<<dim3(MTOK / 128, DD / 128), 256, SMEM>>>(
        p_xpad, p_wi_h, p_wi_l, b_in, nullptr, p_h, MTOK, DD, CCP, CCP);

    for (int l = 0; l < LLY; ++l) {
        gemm_tc<0><<<dim3(MALL / 128, (3 * DD) / 128), 256, SMEM>>>(
            p_h, p_wq_h + (size_t)l * 3 * DD * DD, p_wq_l + (size_t)l * 3 * DD * DD,
            bqkv + (size_t)l * 3 * DD, nullptr, p_qkv, MALL, 3 * DD, DD, DD);
        attn_kernel<<<BB * HHD, 128>>>();
        gemm_tc<2><<<dim3(MALL / 128, DD / 128), 256, SMEM>>>(
            p_o, p_wo_h + (size_t)l * DD * DD, p_wo_l + (size_t)l * DD * DD,
            bo + (size_t)l * DD, p_h, p_h, MALL, DD, DD, DD);
        ln_kernel<0><<<MALL, 256>>>(p_h, p_h, ln1_g + l * DD, ln1_b + l * DD, DD, DD);
        gemm_tc<1><<<dim3(MALL / 128, FFD / 128), 256, SMEM>>>(
            p_h, p_w1_h + (size_t)l * FFD * DD, p_w1_l + (size_t)l * FFD * DD,
            b1 + (size_t)l * FFD, nullptr, p_ff, MALL, FFD, DD, DD);
        gemm_tc<2><<<dim3(MALL / 128, DD / 128), 256, SMEM>>>(
            p_ff, p_w2_h + (size_t)l * DD * FFD, p_w2_l + (size_t)l * DD * FFD,
            b2 + (size_t)l * DD, p_h, p_h, MALL, DD, FFD, FFD);
        ln_kernel<0><<<MALL, 256>>>(p_h, p_h, ln2_g + l * DD, ln2_b + l * DD, DD, DD);
    }

    // cls row LN -> z_e
    ln_kernel<0><<<BB, 256>>>(p_h, p_cls, lnf_g, lnf_b, (size_t)TTT * DD, DD);
    gemm_tc<0><<<dim3(BB / 128, EED / 128), 256, SMEM>>>(
        p_cls, p_wout_h, p_wout_l, b_out, nullptr, p_ze, BB, EED, DD, DD);

    // VQ
    vq_kernel<<<BB, 128>>>(codebook);

    // decoder
    gemm_tc<0><<<dim3(BB / 128, DD / 128), 256, SMEM>>>(
        p_zqst, p_wd1_h, p_wd1_l, bd1, nullptr, p_d1, BB, DD, EED, EED);
    ln_kernel<1><<<BB, 256>>>(p_d1, p_d1, lnd_g, lnd_b, DD, DD);
    gemm_tc<1><<<dim3(BB / 128, EED / 128), 256, SMEM>>>(
        p_d1, p_wd2_h, p_wd2_l, bd2, nullptr, p_d2, BB, EED, DD, DD);
    head_kernel<<<BB, 128>>>(Wd3, bd3, out, out_size);

    idx_copy_kernel<<<(BB + 255) / 256, 256>>>(out, out_size);
    finalize_kernel<<<1, 1024>>>(out, out_size);
}

// round 10
// speedup vs baseline: 1.4156x; 1.0610x over previous
#include <cuda_runtime.h>
#include <math.h>
#include <stdint.h>

// ---------------- problem constants ----------------
constexpr int BB  = 2048;
constexpr int SS  = 64;
constexpr int CC  = 142;
constexpr int CCP = 144;  // padded K for input projection (16-float multiple)
constexpr int DD  = 256;
constexpr int HHD = 8;
constexpr int DHH = 32;
constexpr int FFD = 512;
constexpr int LLY = 3;
constexpr int EED = 128;
constexpr int KKC = 1024;
constexpr int TTT = 65;
#define EPSLN 1e-5f

// ---------------- scratch (device globals; no allocs allowed) ----------------
__device__ float g_h   [(size_t)BB * TTT * DD];
__device__ float g_qkv [(size_t)BB * TTT * 3 * DD];
__device__ float g_o   [(size_t)BB * TTT * DD];
__device__ float g_ff  [(size_t)BB * TTT * FFD];
__device__ float g_cls [BB * DD];
__device__ float g_ze  [BB * EED];
__device__ float g_zqst[BB * EED];
__device__ float g_d1  [BB * DD];
__device__ float g_d2  [BB * EED];
__device__ float g_lossrow[BB];
__device__ float g_hist[KKC];
__device__ int   g_idx [BB];
__device__ float g_pe  [SS * DD];

// padded input + pre-split tf32 weight planes
__device__ float g_xpad [(size_t)BB * SS * CCP];
__device__ float g_wi_h [DD * CCP];
__device__ float g_wi_l [DD * CCP];
__device__ float g_wq_h [LLY * 3 * DD * DD];
__device__ float g_wq_l [LLY * 3 * DD * DD];
__device__ float g_wo_h [LLY * DD * DD];
__device__ float g_wo_l [LLY * DD * DD];
__device__ float g_w1_h [LLY * FFD * DD];
__device__ float g_w1_l [LLY * FFD * DD];
__device__ float g_w2_h [LLY * DD * FFD];
__device__ float g_w2_l [LLY * DD * FFD];
__device__ float g_wout_h [EED * DD];
__device__ float g_wout_l [EED * DD];
__device__ float g_wd1_h [DD * EED];
__device__ float g_wd1_l [DD * EED];
__device__ float g_wd2_h [EED * DD];
__device__ float g_wd2_l [EED * DD];

// ---------------- helpers ----------------
__device__ __forceinline__ float gelu_exact(float v) {
    return 0.5f * v * (1.f + erff(v * 0.70710678118654752f));
}

__device__ __forceinline__ void split2(float x, uint32_t& h, uint32_t& l) {
    uint32_t hb; asm("cvt.rna.tf32.f32 %0, %1;" : "=r"(hb) : "f"(x));
    float hf = __uint_as_float(hb);
    asm("cvt.rna.tf32.f32 %0, %1;" : "=r"(l) : "f"(x - hf));
    h = hb;
}

__device__ __forceinline__ void mma1688(float* d, const uint32_t* a, const uint32_t* b) {
    asm volatile(
        "mma.sync.aligned.m16n8k8.row.col.f32.tf32.tf32.f32 "
        "{%0,%1,%2,%3}, {%4,%5,%6,%7}, {%8,%9}, {%0,%1,%2,%3};"
        : "+f"(d[0]), "+f"(d[1]), "+f"(d[2]), "+f"(d[3])
        : "r"(a[0]), "r"(a[1]), "r"(a[2]), "r"(a[3]), "r"(b[0]), "r"(b[1]));
}

__device__ __forceinline__ void cp16(uint32_t dst, const void* src) {
    asm volatile("cp.async.cg.shared.global [%0], [%1], 16;\n"
                 :: "r"(dst), "l"(src) : "memory");
}
__device__ __forceinline__ void cp_async_commit() {
    asm volatile("cp.async.commit_group;\n" ::: "memory");
}
__device__ __forceinline__ void cp_async_wait0() {
    asm volatile("cp.async.wait_group 0;\n" ::: "memory");
}

// ---------------- prep kernels ----------------
__global__ void pad_x_kernel(const float* __restrict__ x) {
    int i = blockIdx.x * blockDim.x + threadIdx.x;
    if (i < BB * SS * CCP) {
        int r = i / CCP, c = i - r * CCP;
        g_xpad[i] = (c < CC) ? x[(size_t)r * CC + c] : 0.f;
    }
}

__global__ void splitw_kernel(const float* __restrict__ in,
                              float* __restrict__ oh, float* __restrict__ ol,
                              int N, int K, int Kp) {
    int i = blockIdx.x * blockDim.x + threadIdx.x;
    if (i < N * Kp) {
        int r = i / Kp, c = i - r * Kp;
        float v = (c < K) ? in[(size_t)r * K + c] : 0.f;
        uint32_t h, l; split2(v, h, l);
        oh[i] = __uint_as_float(h);
        ol[i] = __uint_as_float(l);
    }
}

// ---------------- misc init ----------------
__global__ void pe_init_kernel() {
    int i = blockIdx.x * blockDim.x + threadIdx.x;
    if (i < SS * DD) {
        int s = i >> 8, n = i & 255;
        double div = exp((double)(n & ~1) * (-9.210340371976184 / 256.0));
        double v = (n & 1) ? cos((double)s * div) : sin((double)s * div);
        g_pe[i] = (float)v;
    }
}

__global__ void zero_kernel(float* out, int out_size) {
    int i = blockIdx.x * blockDim.x + threadIdx.x;
    if (i < out_size) out[i] = 0.f;
    if (i < KKC) g_hist[i] = 0.f;
}

__global__ void cls_fill_kernel(const float* __restrict__ cls) {
    int i = blockIdx.x * blockDim.x + threadIdx.x;
    if (i < BB * DD) {
        int b = i >> 8, d = i & 255;
        g_h[(size_t)b * TTT * DD + d] = cls[d];
    }
}

// ---------------- 3xTF32 tensor-core GEMM, pre-split B planes ----------------
template <int EPI>
__global__ __launch_bounds__(256, 2) void gemm_tc(
    const float* __restrict__ A, const float* __restrict__ Bh, const float* __restrict__ Bl,
    const float* __restrict__ bias, const float* __restrict__ resid,
    float* __restrict__ C, int M, int N, int Kp, int lda)
{
    extern __shared__ float dsm[];   // [6][128][20] : A0,A1,Bh0,Bh1,Bl0,Bl1

    const int tid  = threadIdx.x;
    const int warp = tid >> 5, lane = tid & 31;
    const int g    = lane >> 2;
    const int tg   = lane & 3;
    const int wm   = (warp >> 1) * 32;
    const int wn   = (warp & 1) * 64;
    const int m0   = blockIdx.x * 128, n0 = blockIdx.y * 128;
    const int ldb  = Kp;

    float acc[2][8][4];
#pragma unroll
    for (int i = 0; i < 2; ++i)
#pragma unroll
        for (int j = 0; j < 8; ++j)
#pragma unroll
            for (int c = 0; c < 4; ++c) acc[i][j][c] = 0.f;

    const uint32_t sbase = (uint32_t)__cvta_generic_to_shared(dsm);
    const uint32_t stageB = 128 * 20 * 4;

    auto fill = [&](int stage, int k0) {
        const uint32_t dA  = sbase + stage * stageB;
        const uint32_t dBh = sbase + (2 + stage) * stageB;
        const uint32_t dBl = sbase + (4 + stage) * stageB;
#pragma unroll
        for (int c = 0; c < 2; ++c) {
            const int chunk = tid + c * 256;
            const int row = chunk >> 2;
            const int kl  = (chunk & 3) * 4;
            const uint32_t doff = (uint32_t)(row * 20 + kl) * 4;
            const int kg = k0 + kl;
            cp16(dA  + doff, A  + (size_t)(m0 + row) * lda + kg);
            cp16(dBh + doff, Bh + (size_t)(n0 + row) * ldb + kg);
            cp16(dBl + doff, Bl + (size_t)(n0 + row) * ldb + kg);
        }
    };

    const int NT = Kp >> 4;

    fill(0, 0);
    cp_async_commit();
    cp_async_wait0();
    __syncthreads();

    for (int t = 0; t < NT; ++t) {
        const int cur = t & 1;
        if (t + 1 < NT) {
            fill((t + 1) & 1, (t + 1) * 16);
            cp_async_commit();
        }

        const float* Ac  = dsm + cur * 2560;
        const float* Bhc = dsm + (2 + cur) * 2560;
        const float* Blc = dsm + (4 + cur) * 2560;

#pragma unroll
        for (int kk = 0; kk < 16; kk += 8) {
            uint32_t ah[2][4], al[2][4];
#pragma unroll
            for (int mt = 0; mt < 2; ++mt) {
                const int mr = wm + mt * 16;
                split2(Ac[(mr + g    ) * 20 + kk + tg    ], ah[mt][0], al[mt][0]);
                split2(Ac[(mr + g + 8) * 20 + kk + tg    ], ah[mt][1], al[mt][1]);
                split2(Ac[(mr + g    ) * 20 + kk + tg + 4], ah[mt][2], al[mt][2]);
                split2(Ac[(mr + g + 8) * 20 + kk + tg + 4], ah[mt][3], al[mt][3]);
            }
#pragma unroll
            for (int nt = 0; nt < 8; ++nt) {
                const int nc = wn + nt * 8;
                uint32_t bh[2], bl[2];
                bh[0] = __float_as_uint(Bhc[(nc + g) * 20 + kk + tg    ]);
                bh[1] = __float_as_uint(Bhc[(nc + g) * 20 + kk + tg + 4]);
                bl[0] = __float_as_uint(Blc[(nc + g) * 20 + kk + tg    ]);
                bl[1] = __float_as_uint(Blc[(nc + g) * 20 + kk + tg + 4]);
#pragma unroll
                for (int mt = 0; mt < 2; ++mt) {
                    mma1688(acc[mt][nt], ah[mt], bh);
                    mma1688(acc[mt][nt], ah[mt], bl);
                    mma1688(acc[mt][nt], al[mt], bh);
                }
            }
        }

        if (t + 1 < NT) cp_async_wait0();
        __syncthreads();
    }

#pragma unroll
    for (int mt = 0; mt < 2; ++mt) {
#pragma unroll
        for (int nt = 0; nt < 8; ++nt) {
#pragma unroll
            for (int c = 0; c < 4; ++c) {
                const int m = m0 + wm + mt * 16 + g + ((c >> 1) ? 8 : 0);
                const int n = n0 + wn + nt * 8 + 2 * tg + (c & 1);
                float v = acc[mt][nt][c] + bias[n];
                if (EPI == 1) {
                    C[(size_t)m * N + n] = gelu_exact(v);
                } else if (EPI == 2) {
                    v += resid[(size_t)m * N + n];
                    C[(size_t)m * N + n] = v;
                } else if (EPI == 3) {
                    const int bi = m >> 6;
                    const int s  = m & 63;
                    v += g_pe[s * DD + n];
                    C[(size_t)(m + bi + 1) * N + n] = v;
                } else {
                    C[(size_t)m * N + n] = v;
                }
            }
        }
    }
}

// ---------------- attention: warp-parallel, block per (b, head) ----------------
// 256 threads = 8 warps; warp w handles queries qi = w, w+8, ...
// Scores: lane l covers ki = l and l+32 (lane 0 also ki=64). Output: lane = dim.
__global__ __launch_bounds__(256) void attn_kernel() {
    const int bh = blockIdx.x;
    const int b = bh >> 3, hd = bh & 7;
    __shared__ float Qs[TTT][DHH + 1];
    __shared__ float Ks[TTT][DHH + 1];
    __shared__ float Vs[TTT][DHH + 1];
    __shared__ float Ps[8][TTT + 1];
    const int tid = threadIdx.x;
    const int w = tid >> 5, l = tid & 31;
    const size_t base = (size_t)b * TTT * 768;

    for (int i = tid; i < TTT * DHH; i += 256) {
        int t = i >> 5, d = i & 31;
        size_t rb = base + (size_t)t * 768 + hd * 32 + d;
        Qs[t][d] = g_qkv[rb];
        Ks[t][d] = g_qkv[rb + 256];
        Vs[t][d] = g_qkv[rb + 512];
    }
    __syncthreads();

    for (int qi = w; qi < TTT; qi += 8) {
        // q into registers (broadcast smem reads)
        float q[DHH];
#pragma unroll
        for (int d = 0; d < DHH; ++d) q[d] = Qs[qi][d];

        // scores for ki = l, l+32 (all valid), ki = 64 on lane 0
        float s0 = 0.f, s1 = 0.f, s2 = 0.f;
#pragma unroll
        for (int d = 0; d < DHH; ++d) {
            s0 = fmaf(q[d], Ks[l][d], s0);
            s1 = fmaf(q[d], Ks[l + 32][d], s1);
        }
        if (l == 0) {
#pragma unroll
            for (int d = 0; d < DHH; ++d) s2 = fmaf(q[d], Ks[64][d], s2);
        }
        const float scale = 0.17677669529663687f;   // 1/sqrt(32)
        s0 *= scale; s1 *= scale; s2 *= scale;

        float mx = fmaxf(s0, s1);
        if (l == 0) mx = fmaxf(mx, s2);
#pragma unroll
        for (int o = 16; o > 0; o >>= 1) mx = fmaxf(mx, __shfl_xor_sync(0xffffffffu, mx, o));

        float e0 = expf(s0 - mx);
        float e1 = expf(s1 - mx);
        float e2 = (l == 0) ? expf(s2 - mx) : 0.f;
        float sum = e0 + e1 + e2;
#pragma unroll
        for (int o = 16; o > 0; o >>= 1) sum += __shfl_xor_sync(0xffffffffu, sum, o);
        const float inv = 1.f / sum;

        Ps[w][l]      = e0 * inv;
        Ps[w][l + 32] = e1 * inv;
        if (l == 0) Ps[w][64] = e2 * inv;
        __syncwarp();

        // output: lane = dim
        float acc = 0.f;
#pragma unroll 5
        for (int ki = 0; ki < TTT; ++ki)
            acc = fmaf(Ps[w][ki], Vs[ki][l], acc);

        g_o[((size_t)b * TTT + qi) * DD + hd * 32 + l] = acc;
        __syncwarp();
    }
}

// ---------------- LayerNorm: warp per row, 8 rows per block, shfl-only ----------------
template <int GELU>
__global__ __launch_bounds__(256) void ln_kernel(
    const float* __restrict__ in, float* __restrict__ out,
    const float* __restrict__ gamma, const float* __restrict__ beta,
    size_t inStride, size_t outStride)
{
    const int w = threadIdx.x >> 5, l = threadIdx.x & 31;
    const size_t row = (size_t)blockIdx.x * 8 + w;
    const float* rp = in + row * inStride;

    float4 a = *(const float4*)(rp + l * 4);
    float4 c = *(const float4*)(rp + 128 + l * 4);

    float s = a.x + a.y + a.z + a.w + c.x + c.y + c.z + c.w;
#pragma unroll
    for (int o = 16; o > 0; o >>= 1) s += __shfl_xor_sync(0xffffffffu, s, o);
    const float mean = s * (1.f / 256.f);

    a.x -= mean; a.y -= mean; a.z -= mean; a.w -= mean;
    c.x -= mean; c.y -= mean; c.z -= mean; c.w -= mean;
    float s2 = a.x * a.x + a.y * a.y + a.z * a.z + a.w * a.w
             + c.x * c.x + c.y * c.y + c.z * c.z + c.w * c.w;
#pragma unroll
    for (int o = 16; o > 0; o >>= 1) s2 += __shfl_xor_sync(0xffffffffu, s2, o);
    const float r = rsqrtf(s2 * (1.f / 256.f) + EPSLN);

    float4 ga = *(const float4*)(gamma + l * 4);
    float4 gc = *(const float4*)(gamma + 128 + l * 4);
    float4 ba = *(const float4*)(beta + l * 4);
    float4 bc = *(const float4*)(beta + 128 + l * 4);

    float4 ya, yc;
    ya.x = a.x * r * ga.x + ba.x;  ya.y = a.y * r * ga.y + ba.y;
    ya.z = a.z * r * ga.z + ba.z;  ya.w = a.w * r * ga.w + ba.w;
    yc.x = c.x * r * gc.x + bc.x;  yc.y = c.y * r * gc.y + bc.y;
    yc.z = c.z * r * gc.z + bc.z;  yc.w = c.w * r * gc.w + bc.w;

    if (GELU) {
        ya.x = gelu_exact(ya.x); ya.y = gelu_exact(ya.y);
        ya.z = gelu_exact(ya.z); ya.w = gelu_exact(ya.w);
        yc.x = gelu_exact(yc.x); yc.y = gelu_exact(yc.y);
        yc.z = gelu_exact(yc.z); yc.w = gelu_exact(yc.w);
    }

    float* op = out + row * outStride;
    *(float4*)(op + l * 4) = ya;
    *(float4*)(op + 128 + l * 4) = yc;
}

// ---------------- VQ ----------------
__global__ __launch_bounds__(128) void vq_kernel(const float* __restrict__ cb) {
    const int row = blockIdx.x, t = threadIdx.x;
    __shared__ float zs[EED];
    __shared__ float bd[128];
    __shared__ int   bi[128];

    zs[t] = g_ze[row * EED + t];
    __syncthreads();

    float ze2 = 0.f;
    for (int d = 0; d < EED; ++d) ze2 = fmaf(zs[d], zs[d], ze2);

    float best = 3.4e38f;
    int bestk = 0;
    for (int k = t; k < KKC; k += 128) {
        const float* c = cb + (size_t)k * EED;
        float dot = 0.f, c2 = 0.f;
        for (int d = 0; d < EED; ++d) {
            float cv = c[d];
            dot = fmaf(cv, zs[d], dot);
            c2  = fmaf(cv, cv, c2);
        }
        float d2 = (ze2 - 2.f * dot) + c2;
        if (d2 < best) { best = d2; bestk = k; }
    }
    bd[t] = best; bi[t] = bestk;
    __syncthreads();
    for (int o = 64; o > 0; o >>= 1) {
        if (t < o) {
            float ob = bd[t + o]; int oi = bi[t + o];
            if (ob < bd[t] || (ob == bd[t] && oi < bi[t])) { bd[t] = ob; bi[t] = oi; }
        }
        __syncthreads();
    }
    const int widx = bi[0];
    __syncthreads();

    const float zq  = cb[(size_t)widx * EED + t];
    const float zev = zs[t];
    g_zqst[row * EED + t] = zev + (zq - zev);
    const float df = zq - zev;
    bd[t] = df * df;
    __syncthreads();
    for (int o = 64; o > 0; o >>= 1) {
        if (t < o) bd[t] += bd[t + o];
        __syncthreads();
    }
    if (t == 0) {
        g_idx[row] = widx;
        g_lossrow[row] = bd[0];
        atomicAdd(&g_hist[widx], 1.0f);
    }
}

// ---------------- final 2-wide head ----------------
__global__ __launch_bounds__(128) void head_kernel(
    const float* __restrict__ Wd3, const float* __restrict__ bd3,
    float* __restrict__ out, int out_size)
{
    const int row = blockIdx.x, t = threadIdx.x;
    __shared__ float sred[4];
    const float x = g_d2[row * EED + t];
    for (int c = 0; c < 2; ++c) {
        float p = x * Wd3[c * EED + t];
#pragma unroll
        for (int o = 16; o > 0; o >>= 1) p += __shfl_xor_sync(0xffffffffu, p, o);
        if ((t & 31) == 0) sred[t >> 5] = p;
        __syncthreads();
        if (t == 0) {
            float tot = sred[0] + sred[1] + sred[2] + sred[3];
            int oi = row * 2 + c;
            if (oi < out_size) out[oi] = tot + bd3[c];
        }
        __syncthreads();
    }
}

__global__ void idx_copy_kernel(float* out, int out_size) {
    int i = blockIdx.x * blockDim.x + threadIdx.x;
    if (i < BB) {
        int oi = 2 * BB + i;
        if (oi < out_size) out[oi] = (float)g_idx[i];
    }
}

__global__ __launch_bounds__(1024) void finalize_kernel(float* out, int out_size) {
    const int t = threadIdx.x;
    __shared__ float sh[1024];

    float p = g_hist[t] * (1.f / 2048.f);
    sh[t] = p * logf(p + 1e-10f);
    __syncthreads();
    for (int o = 512; o > 0; o >>= 1) {
        if (t < o) sh[t] += sh[t + o];
        __syncthreads();
    }
    const float perp = expf(-sh[0]);
    __syncthreads();

    sh[t] = g_lossrow[t] + g_lossrow[t + 1024];
    __syncthreads();
    for (int o = 512; o > 0; o >>= 1) {
        if (t < o) sh[t] += sh[t + o];
        __syncthreads();
    }
    if (t == 0) {
        int li = 2 * BB + BB;
        if (li < out_size)     out[li]     = 0.1f * sh[0] / (float)(BB * EED);
        if (li + 1 < out_size) out[li + 1] = perp;
    }
}

// ---------------- launch ----------------
extern "C" void kernel_launch(void* const* d_in, const int* in_sizes, int n_in,
                              void* d_out, int out_size)
{
    const float* x         = (const float*)d_in[0];
    const float* W_in      = (const float*)d_in[1];
    const float* b_in      = (const float*)d_in[2];
    const float* cls_token = (const float*)d_in[3];
    const float* Wqkv      = (const float*)d_in[4];
    const float* bqkv      = (const float*)d_in[5];
    const float* Wo        = (const float*)d_in[6];
    const float* bo        = (const float*)d_in[7];
    const float* W1        = (const float*)d_in[8];
    const float* b1        = (const float*)d_in[9];
    const float* W2        = (const float*)d_in[10];
    const float* b2        = (const float*)d_in[11];
    const float* ln1_g     = (const float*)d_in[12];
    const float* ln1_b     = (const float*)d_in[13];
    const float* ln2_g     = (const float*)d_in[14];
    const float* ln2_b     = (const float*)d_in[15];
    const float* lnf_g     = (const float*)d_in[16];
    const float* lnf_b     = (const float*)d_in[17];
    const float* W_out     = (const float*)d_in[18];
    const float* b_out     = (const float*)d_in[19];
    const float* codebook  = (const float*)d_in[20];
    const float* Wd1       = (const float*)d_in[21];
    const float* bd1       = (const float*)d_in[22];
    const float* lnd_g     = (const float*)d_in[23];
    const float* lnd_b     = (const float*)d_in[24];
    const float* Wd2       = (const float*)d_in[25];
    const float* bd2       = (const float*)d_in[26];
    const float* Wd3       = (const float*)d_in[27];
    const float* bd3       = (const float*)d_in[28];
    float* out = (float*)d_out;

    float *p_h, *p_qkv, *p_o, *p_ff, *p_cls, *p_ze, *p_zqst, *p_d1, *p_d2, *p_xpad;
    float *p_wi_h, *p_wi_l, *p_wq_h, *p_wq_l, *p_wo_h, *p_wo_l;
    float *p_w1_h, *p_w1_l, *p_w2_h, *p_w2_l;
    float *p_wout_h, *p_wout_l, *p_wd1_h, *p_wd1_l, *p_wd2_h, *p_wd2_l;
    cudaGetSymbolAddress((void**)&p_h,    g_h);
    cudaGetSymbolAddress((void**)&p_qkv,  g_qkv);
    cudaGetSymbolAddress((void**)&p_o,    g_o);
    cudaGetSymbolAddress((void**)&p_ff,   g_ff);
    cudaGetSymbolAddress((void**)&p_cls,  g_cls);
    cudaGetSymbolAddress((void**)&p_ze,   g_ze);
    cudaGetSymbolAddress((void**)&p_zqst, g_zqst);
    cudaGetSymbolAddress((void**)&p_d1,   g_d1);
    cudaGetSymbolAddress((void**)&p_d2,   g_d2);
    cudaGetSymbolAddress((void**)&p_xpad, g_xpad);
    cudaGetSymbolAddress((void**)&p_wi_h, g_wi_h);
    cudaGetSymbolAddress((void**)&p_wi_l, g_wi_l);
    cudaGetSymbolAddress((void**)&p_wq_h, g_wq_h);
    cudaGetSymbolAddress((void**)&p_wq_l, g_wq_l);
    cudaGetSymbolAddress((void**)&p_wo_h, g_wo_h);
    cudaGetSymbolAddress((void**)&p_wo_l, g_wo_l);
    cudaGetSymbolAddress((void**)&p_w1_h, g_w1_h);
    cudaGetSymbolAddress((void**)&p_w1_l, g_w1_l);
    cudaGetSymbolAddress((void**)&p_w2_h, g_w2_h);
    cudaGetSymbolAddress((void**)&p_w2_l, g_w2_l);
    cudaGetSymbolAddress((void**)&p_wout_h, g_wout_h);
    cudaGetSymbolAddress((void**)&p_wout_l, g_wout_l);
    cudaGetSymbolAddress((void**)&p_wd1_h, g_wd1_h);
    cudaGetSymbolAddress((void**)&p_wd1_l, g_wd1_l);
    cudaGetSymbolAddress((void**)&p_wd2_h, g_wd2_h);
    cudaGetSymbolAddress((void**)&p_wd2_l, g_wd2_l);

    const int MTOK = BB * SS;        // 131072
    const int MALL = BB * TTT;       // 133120
    const int SMEM = 6 * 128 * 20 * 4;  // 61440 bytes dynamic

    cudaFuncSetAttribute(gemm_tc<0>, cudaFuncAttributeMaxDynamicSharedMemorySize, SMEM);
    cudaFuncSetAttribute(gemm_tc<1>, cudaFuncAttributeMaxDynamicSharedMemorySize, SMEM);
    cudaFuncSetAttribute(gemm_tc<2>, cudaFuncAttributeMaxDynamicSharedMemorySize, SMEM);
    cudaFuncSetAttribute(gemm_tc<3>, cudaFuncAttributeMaxDynamicSharedMemorySize, SMEM);

    {
        int n = out_size > KKC ? out_size : KKC;
        zero_kernel<<<(n + 255) / 256, 256>>>(out, out_size);
    }
    pe_init_kernel<<<(SS * DD + 255) / 256, 256>>>();
    cls_fill_kernel<<<(BB * DD + 255) / 256, 256>>>(cls_token);

    // ---- prep: pad x, split all weights into tf32 hi/lo planes ----
    pad_x_kernel<<<(BB * SS * CCP + 255) / 256, 256>>>(x);
    auto splitw = [&](const float* in, float* oh, float* ol, int N, int K, int Kp) {
        splitw_kernel<<<(N * Kp + 255) / 256, 256>>>(in, oh, ol, N, K, Kp);
    };
    splitw(W_in,  p_wi_h,  p_wi_l,  DD, CC, CCP);
    splitw(Wqkv,  p_wq_h,  p_wq_l,  LLY * 3 * DD, DD, DD);
    splitw(Wo,    p_wo_h,  p_wo_l,  LLY * DD, DD, DD);
    splitw(W1,    p_w1_h,  p_w1_l,  LLY * FFD, DD, DD);
    splitw(W2,    p_w2_h,  p_w2_l,  LLY * DD, FFD, FFD);
    splitw(W_out, p_wout_h, p_wout_l, EED, DD, DD);
    splitw(Wd1,   p_wd1_h, p_wd1_l, DD, EED, EED);
    splitw(Wd2,   p_wd2_h, p_wd2_l, EED, DD, DD);

    // ---- input projection + PE, scattered into h rows (skipping cls rows) ----
    gemm_tc<3><<<dim3(MTOK / 128, DD / 128), 256, SMEM>>>(
        p_xpad, p_wi_h, p_wi_l, b_in, nullptr, p_h, MTOK, DD, CCP, CCP);

    for (int l = 0; l < LLY; ++l) {
        gemm_tc<0><<<dim3(MALL / 128, (3 * DD) / 128), 256, SMEM>>>(
            p_h, p_wq_h + (size_t)l * 3 * DD * DD, p_wq_l + (size_t)l * 3 * DD * DD,
            bqkv + (size_t)l * 3 * DD, nullptr, p_qkv, MALL, 3 * DD, DD, DD);
        attn_kernel<<<BB * HHD, 256>>>();
        gemm_tc<2><<<dim3(MALL / 128, DD / 128), 256, SMEM>>>(
            p_o, p_wo_h + (size_t)l * DD * DD, p_wo_l + (size_t)l * DD * DD,
            bo + (size_t)l * DD, p_h, p_h, MALL, DD, DD, DD);
        ln_kernel<0><<<MALL / 8, 256>>>(p_h, p_h, ln1_g + l * DD, ln1_b + l * DD, DD, DD);
        gemm_tc<1><<<dim3(MALL / 128, FFD / 128), 256, SMEM>>>(
            p_h, p_w1_h + (size_t)l * FFD * DD, p_w1_l + (size_t)l * FFD * DD,
            b1 + (size_t)l * FFD, nullptr, p_ff, MALL, FFD, DD, DD);
        gemm_tc<2><<<dim3(MALL / 128, DD / 128), 256, SMEM>>>(
            p_ff, p_w2_h + (size_t)l * DD * FFD, p_w2_l + (size_t)l * DD * FFD,
            b2 + (size_t)l * DD, p_h, p_h, MALL, DD, FFD, FFD);
        ln_kernel<0><<<MALL / 8, 256>>>(p_h, p_h, ln2_g + l * DD, ln2_b + l * DD, DD, DD);
    }

    // cls row LN -> z_e
    ln_kernel<0><<<BB / 8, 256>>>(p_h, p_cls, lnf_g, lnf_b, (size_t)TTT * DD, DD);
    gemm_tc<0><<<dim3(BB / 128, EED / 128), 256, SMEM>>>(
        p_cls, p_wout_h, p_wout_l, b_out, nullptr, p_ze, BB, EED, DD, DD);

    // VQ
    vq_kernel<<<BB, 128>>>(codebook);

    // decoder
    gemm_tc<0><<<dim3(BB / 128, DD / 128), 256, SMEM>>>(
        p_zqst, p_wd1_h, p_wd1_l, bd1, nullptr, p_d1, BB, DD, EED, EED);
    ln_kernel<1><<<BB / 8, 256>>>(p_d1, p_d1, lnd_g, lnd_b, DD, DD);
    gemm_tc<1><<<dim3(BB / 128, EED / 128), 256, SMEM>>>(
        p_d1, p_wd2_h, p_wd2_l, bd2, nullptr, p_d2, BB, EED, DD, DD);
    head_kernel<<<BB, 128>>>(Wd3, bd3, out, out_size);

    idx_copy_kernel<<<(BB + 255) / 256, 256>>>(out, out_size);
    finalize_kernel<<<1, 1024>>>(out, out_size);
}

// round 11
// speedup vs baseline: 1.4183x; 1.0019x over previous
#include <cuda_runtime.h>
#include <math.h>
#include <stdint.h>

// ---------------- problem constants ----------------
constexpr int BB  = 2048;
constexpr int SS  = 64;
constexpr int CC  = 142;
constexpr int CCP = 144;  // padded K for input projection (16-float multiple)
constexpr int DD  = 256;
constexpr int HHD = 8;
constexpr int DHH = 32;
constexpr int FFD = 512;
constexpr int LLY = 3;
constexpr int EED = 128;
constexpr int KKC = 1024;
constexpr int TTT = 65;
#define EPSLN 1e-5f

// ---------------- scratch (device globals; no allocs allowed) ----------------
__device__ float g_h   [(size_t)BB * TTT * DD];
__device__ float g_qkv [(size_t)BB * TTT * 3 * DD];
__device__ float g_o   [(size_t)BB * TTT * DD];
__device__ float g_ff  [(size_t)BB * TTT * FFD];
__device__ float g_cls [BB * DD];
__device__ float g_ze  [BB * EED];
__device__ float g_zqst[BB * EED];
__device__ float g_d1  [BB * DD];
__device__ float g_d2  [BB * EED];
__device__ float g_lossrow[BB];
__device__ float g_hist[KKC];
__device__ int   g_idx [BB];
__device__ float g_pe  [SS * DD];

// padded input + pre-split tf32 weight planes
__device__ float g_xpad [(size_t)BB * SS * CCP];
__device__ float g_wi_h [DD * CCP];
__device__ float g_wi_l [DD * CCP];
__device__ float g_wq_h [LLY * 3 * DD * DD];
__device__ float g_wq_l [LLY * 3 * DD * DD];
__device__ float g_wo_h [LLY * DD * DD];
__device__ float g_wo_l [LLY * DD * DD];
__device__ float g_w1_h [LLY * FFD * DD];
__device__ float g_w1_l [LLY * FFD * DD];
__device__ float g_w2_h [LLY * DD * FFD];
__device__ float g_w2_l [LLY * DD * FFD];
__device__ float g_wout_h [EED * DD];
__device__ float g_wout_l [EED * DD];
__device__ float g_wd1_h [DD * EED];
__device__ float g_wd1_l [DD * EED];
__device__ float g_wd2_h [EED * DD];
__device__ float g_wd2_l [EED * DD];

// ---------------- helpers ----------------
__device__ __forceinline__ float gelu_exact(float v) {
    return 0.5f * v * (1.f + erff(v * 0.70710678118654752f));
}

__device__ __forceinline__ void split2(float x, uint32_t& h, uint32_t& l) {
    uint32_t hb; asm("cvt.rna.tf32.f32 %0, %1;" : "=r"(hb) : "f"(x));
    float hf = __uint_as_float(hb);
    asm("cvt.rna.tf32.f32 %0, %1;" : "=r"(l) : "f"(x - hf));
    h = hb;
}

__device__ __forceinline__ void mma1688(float* d, const uint32_t* a, const uint32_t* b) {
    asm volatile(
        "mma.sync.aligned.m16n8k8.row.col.f32.tf32.tf32.f32 "
        "{%0,%1,%2,%3}, {%4,%5,%6,%7}, {%8,%9}, {%0,%1,%2,%3};"
        : "+f"(d[0]), "+f"(d[1]), "+f"(d[2]), "+f"(d[3])
        : "r"(a[0]), "r"(a[1]), "r"(a[2]), "r"(a[3]), "r"(b[0]), "r"(b[1]));
}

__device__ __forceinline__ void cp16(uint32_t dst, const void* src) {
    asm volatile("cp.async.cg.shared.global [%0], [%1], 16;\n"
                 :: "r"(dst), "l"(src) : "memory");
}
__device__ __forceinline__ void cp_async_commit() {
    asm volatile("cp.async.commit_group;\n" ::: "memory");
}
__device__ __forceinline__ void cp_async_wait0() {
    asm volatile("cp.async.wait_group 0;\n" ::: "memory");
}

// ---------------- prep kernels ----------------
__global__ void pad_x_kernel(const float* __restrict__ x) {
    int i = blockIdx.x * blockDim.x + threadIdx.x;
    if (i < BB * SS * CCP) {
        int r = i / CCP, c = i - r * CCP;
        g_xpad[i] = (c < CC) ? x[(size_t)r * CC + c] : 0.f;
    }
}

__global__ void splitw_kernel(const float* __restrict__ in,
                              float* __restrict__ oh, float* __restrict__ ol,
                              int N, int K, int Kp) {
    int i = blockIdx.x * blockDim.x + threadIdx.x;
    if (i < N * Kp) {
        int r = i / Kp, c = i - r * Kp;
        float v = (c < K) ? in[(size_t)r * K + c] : 0.f;
        uint32_t h, l; split2(v, h, l);
        oh[i] = __uint_as_float(h);
        ol[i] = __uint_as_float(l);
    }
}

// ---------------- misc init ----------------
__global__ void pe_init_kernel() {
    int i = blockIdx.x * blockDim.x + threadIdx.x;
    if (i < SS * DD) {
        int s = i >> 8, n = i & 255;
        double div = exp((double)(n & ~1) * (-9.210340371976184 / 256.0));
        double v = (n & 1) ? cos((double)s * div) : sin((double)s * div);
        g_pe[i] = (float)v;
    }
}

__global__ void zero_kernel(float* out, int out_size) {
    int i = blockIdx.x * blockDim.x + threadIdx.x;
    if (i < out_size) out[i] = 0.f;
    if (i < KKC) g_hist[i] = 0.f;
}

__global__ void cls_fill_kernel(const float* __restrict__ cls) {
    int i = blockIdx.x * blockDim.x + threadIdx.x;
    if (i < BB * DD) {
        int b = i >> 8, d = i & 255;
        g_h[(size_t)b * TTT * DD + d] = cls[d];
    }
}

// ---------------- 3xTF32 tensor-core GEMM, pre-split B planes ----------------
// Pass-major MMA schedule: chain distance to same accumulator = 8 (covers HMMA latency).
template <int EPI>
__global__ __launch_bounds__(256, 2) void gemm_tc(
    const float* __restrict__ A, const float* __restrict__ Bh, const float* __restrict__ Bl,
    const float* __restrict__ bias, const float* __restrict__ resid,
    float* __restrict__ C, int M, int N, int Kp, int lda)
{
    extern __shared__ float dsm[];   // [6][128][20] : A0,A1,Bh0,Bh1,Bl0,Bl1

    const int tid  = threadIdx.x;
    const int warp = tid >> 5, lane = tid & 31;
    const int g    = lane >> 2;
    const int tg   = lane & 3;
    const int wm   = (warp >> 1) * 32;
    const int wn   = (warp & 1) * 64;
    const int m0   = blockIdx.x * 128, n0 = blockIdx.y * 128;
    const int ldb  = Kp;

    float acc[2][8][4];
#pragma unroll
    for (int i = 0; i < 2; ++i)
#pragma unroll
        for (int j = 0; j < 8; ++j)
#pragma unroll
            for (int c = 0; c < 4; ++c) acc[i][j][c] = 0.f;

    const uint32_t sbase = (uint32_t)__cvta_generic_to_shared(dsm);
    const uint32_t stageB = 128 * 20 * 4;

    auto fill = [&](int stage, int k0) {
        const uint32_t dA  = sbase + stage * stageB;
        const uint32_t dBh = sbase + (2 + stage) * stageB;
        const uint32_t dBl = sbase + (4 + stage) * stageB;
#pragma unroll
        for (int c = 0; c < 2; ++c) {
            const int chunk = tid + c * 256;
            const int row = chunk >> 2;
            const int kl  = (chunk & 3) * 4;
            const uint32_t doff = (uint32_t)(row * 20 + kl) * 4;
            const int kg = k0 + kl;
            cp16(dA  + doff, A  + (size_t)(m0 + row) * lda + kg);
            cp16(dBh + doff, Bh + (size_t)(n0 + row) * ldb + kg);
            cp16(dBl + doff, Bl + (size_t)(n0 + row) * ldb + kg);
        }
    };

    const int NT = Kp >> 4;

    fill(0, 0);
    cp_async_commit();
    cp_async_wait0();
    __syncthreads();

    for (int t = 0; t < NT; ++t) {
        const int cur = t & 1;
        if (t + 1 < NT) {
            fill((t + 1) & 1, (t + 1) * 16);
            cp_async_commit();
        }

        const float* Ac  = dsm + cur * 2560;
        const float* Bhc = dsm + (2 + cur) * 2560;
        const float* Blc = dsm + (4 + cur) * 2560;

#pragma unroll
        for (int kk = 0; kk < 16; kk += 8) {
            uint32_t ah[2][4], al[2][4];
#pragma unroll
            for (int mt = 0; mt < 2; ++mt) {
                const int mr = wm + mt * 16;
                split2(Ac[(mr + g    ) * 20 + kk + tg    ], ah[mt][0], al[mt][0]);
                split2(Ac[(mr + g + 8) * 20 + kk + tg    ], ah[mt][1], al[mt][1]);
                split2(Ac[(mr + g    ) * 20 + kk + tg + 4], ah[mt][2], al[mt][2]);
                split2(Ac[(mr + g + 8) * 20 + kk + tg + 4], ah[mt][3], al[mt][3]);
            }
            // process nt in groups of 4; pass-major within group so consecutive
            // MMAs hit distinct accumulators (chain distance 8)
#pragma unroll
            for (int half = 0; half < 2; ++half) {
                uint32_t bh[4][2], bl[4][2];
#pragma unroll
                for (int j = 0; j < 4; ++j) {
                    const int nc = wn + (half * 4 + j) * 8;
                    bh[j][0] = __float_as_uint(Bhc[(nc + g) * 20 + kk + tg    ]);
                    bh[j][1] = __float_as_uint(Bhc[(nc + g) * 20 + kk + tg + 4]);
                    bl[j][0] = __float_as_uint(Blc[(nc + g) * 20 + kk + tg    ]);
                    bl[j][1] = __float_as_uint(Blc[(nc + g) * 20 + kk + tg + 4]);
                }
#pragma unroll
                for (int j = 0; j < 4; ++j)
#pragma unroll
                    for (int mt = 0; mt < 2; ++mt)
                        mma1688(acc[mt][half * 4 + j], ah[mt], bh[j]);   // hi * hi
#pragma unroll
                for (int j = 0; j < 4; ++j)
#pragma unroll
                    for (int mt = 0; mt < 2; ++mt)
                        mma1688(acc[mt][half * 4 + j], ah[mt], bl[j]);   // hi * lo
#pragma unroll
                for (int j = 0; j < 4; ++j)
#pragma unroll
                    for (int mt = 0; mt < 2; ++mt)
                        mma1688(acc[mt][half * 4 + j], al[mt], bh[j]);   // lo * hi
            }
        }

        if (t + 1 < NT) cp_async_wait0();
        __syncthreads();
    }

#pragma unroll
    for (int mt = 0; mt < 2; ++mt) {
#pragma unroll
        for (int nt = 0; nt < 8; ++nt) {
#pragma unroll
            for (int c = 0; c < 4; ++c) {
                const int m = m0 + wm + mt * 16 + g + ((c >> 1) ? 8 : 0);
                const int n = n0 + wn + nt * 8 + 2 * tg + (c & 1);
                float v = acc[mt][nt][c] + bias[n];
                if (EPI == 1) {
                    C[(size_t)m * N + n] = gelu_exact(v);
                } else if (EPI == 2) {
                    v += resid[(size_t)m * N + n];
                    C[(size_t)m * N + n] = v;
                } else if (EPI == 3) {
                    const int bi = m >> 6;
                    const int s  = m & 63;
                    v += g_pe[s * DD + n];
                    C[(size_t)(m + bi + 1) * N + n] = v;
                } else {
                    C[(size_t)m * N + n] = v;
                }
            }
        }
    }
}

// ---------------- attention: warp-parallel, block per (b, head) ----------------
__global__ __launch_bounds__(256) void attn_kernel() {
    const int bh = blockIdx.x;
    const int b = bh >> 3, hd = bh & 7;
    __shared__ float Qs[TTT][DHH + 1];
    __shared__ float Ks[TTT][DHH + 1];
    __shared__ float Vs[TTT][DHH + 1];
    __shared__ float Ps[8][TTT + 1];
    const int tid = threadIdx.x;
    const int w = tid >> 5, l = tid & 31;
    const size_t base = (size_t)b * TTT * 768;

    for (int i = tid; i < TTT * DHH; i += 256) {
        int t = i >> 5, d = i & 31;
        size_t rb = base + (size_t)t * 768 + hd * 32 + d;
        Qs[t][d] = g_qkv[rb];
        Ks[t][d] = g_qkv[rb + 256];
        Vs[t][d] = g_qkv[rb + 512];
    }
    __syncthreads();

    for (int qi = w; qi < TTT; qi += 8) {
        float q[DHH];
#pragma unroll
        for (int d = 0; d < DHH; ++d) q[d] = Qs[qi][d];

        float s0 = 0.f, s1 = 0.f, s2 = 0.f;
#pragma unroll
        for (int d = 0; d < DHH; ++d) {
            s0 = fmaf(q[d], Ks[l][d], s0);
            s1 = fmaf(q[d], Ks[l + 32][d], s1);
        }
        if (l == 0) {
#pragma unroll
            for (int d = 0; d < DHH; ++d) s2 = fmaf(q[d], Ks[64][d], s2);
        }
        const float scale = 0.17677669529663687f;   // 1/sqrt(32)
        s0 *= scale; s1 *= scale; s2 *= scale;

        float mx = fmaxf(s0, s1);
        if (l == 0) mx = fmaxf(mx, s2);
#pragma unroll
        for (int o = 16; o > 0; o >>= 1) mx = fmaxf(mx, __shfl_xor_sync(0xffffffffu, mx, o));

        float e0 = expf(s0 - mx);
        float e1 = expf(s1 - mx);
        float e2 = (l == 0) ? expf(s2 - mx) : 0.f;
        float sum = e0 + e1 + e2;
#pragma unroll
        for (int o = 16; o > 0; o >>= 1) sum += __shfl_xor_sync(0xffffffffu, sum, o);
        const float inv = 1.f / sum;

        Ps[w][l]      = e0 * inv;
        Ps[w][l + 32] = e1 * inv;
        if (l == 0) Ps[w][64] = e2 * inv;
        __syncwarp();

        float acc = 0.f;
#pragma unroll 5
        for (int ki = 0; ki < TTT; ++ki)
            acc = fmaf(Ps[w][ki], Vs[ki][l], acc);

        g_o[((size_t)b * TTT + qi) * DD + hd * 32 + l] = acc;
        __syncwarp();
    }
}

// ---------------- LayerNorm: warp per row, 8 rows per block, shfl-only ----------------
template <int GELU>
__global__ __launch_bounds__(256) void ln_kernel(
    const float* __restrict__ in, float* __restrict__ out,
    const float* __restrict__ gamma, const float* __restrict__ beta,
    size_t inStride, size_t outStride)
{
    const int w = threadIdx.x >> 5, l = threadIdx.x & 31;
    const size_t row = (size_t)blockIdx.x * 8 + w;
    const float* rp = in + row * inStride;

    float4 a = *(const float4*)(rp + l * 4);
    float4 c = *(const float4*)(rp + 128 + l * 4);

    float s = a.x + a.y + a.z + a.w + c.x + c.y + c.z + c.w;
#pragma unroll
    for (int o = 16; o > 0; o >>= 1) s += __shfl_xor_sync(0xffffffffu, s, o);
    const float mean = s * (1.f / 256.f);

    a.x -= mean; a.y -= mean; a.z -= mean; a.w -= mean;
    c.x -= mean; c.y -= mean; c.z -= mean; c.w -= mean;
    float s2 = a.x * a.x + a.y * a.y + a.z * a.z + a.w * a.w
             + c.x * c.x + c.y * c.y + c.z * c.z + c.w * c.w;
#pragma unroll
    for (int o = 16; o > 0; o >>= 1) s2 += __shfl_xor_sync(0xffffffffu, s2, o);
    const float r = rsqrtf(s2 * (1.f / 256.f) + EPSLN);

    float4 ga = *(const float4*)(gamma + l * 4);
    float4 gc = *(const float4*)(gamma + 128 + l * 4);
    float4 ba = *(const float4*)(beta + l * 4);
    float4 bc = *(const float4*)(beta + 128 + l * 4);

    float4 ya, yc;
    ya.x = a.x * r * ga.x + ba.x;  ya.y = a.y * r * ga.y + ba.y;
    ya.z = a.z * r * ga.z + ba.z;  ya.w = a.w * r * ga.w + ba.w;
    yc.x = c.x * r * gc.x + bc.x;  yc.y = c.y * r * gc.y + bc.y;
    yc.z = c.z * r * gc.z + bc.z;  yc.w = c.w * r * gc.w + bc.w;

    if (GELU) {
        ya.x = gelu_exact(ya.x); ya.y = gelu_exact(ya.y);
        ya.z = gelu_exact(ya.z); ya.w = gelu_exact(ya.w);
        yc.x = gelu_exact(yc.x); yc.y = gelu_exact(yc.y);
        yc.z = gelu_exact(yc.z); yc.w = gelu_exact(yc.w);
    }

    float* op = out + row * outStride;
    *(float4*)(op + l * 4) = ya;
    *(float4*)(op + 128 + l * 4) = yc;
}

// ---------------- VQ ----------------
__global__ __launch_bounds__(128) void vq_kernel(const float* __restrict__ cb) {
    const int row = blockIdx.x, t = threadIdx.x;
    __shared__ float zs[EED];
    __shared__ float bd[128];
    __shared__ int   bi[128];

    zs[t] = g_ze[row * EED + t];
    __syncthreads();

    float ze2 = 0.f;
    for (int d = 0; d < EED; ++d) ze2 = fmaf(zs[d], zs[d], ze2);

    float best = 3.4e38f;
    int bestk = 0;
    for (int k = t; k < KKC; k += 128) {
        const float* c = cb + (size_t)k * EED;
        float dot = 0.f, c2 = 0.f;
        for (int d = 0; d < EED; ++d) {
            float cv = c[d];
            dot = fmaf(cv, zs[d], dot);
            c2  = fmaf(cv, cv, c2);
        }
        float d2 = (ze2 - 2.f * dot) + c2;
        if (d2 < best) { best = d2; bestk = k; }
    }
    bd[t] = best; bi[t] = bestk;
    __syncthreads();
    for (int o = 64; o > 0; o >>= 1) {
        if (t < o) {
            float ob = bd[t + o]; int oi = bi[t + o];
            if (ob < bd[t] || (ob == bd[t] && oi < bi[t])) { bd[t] = ob; bi[t] = oi; }
        }
        __syncthreads();
    }
    const int widx = bi[0];
    __syncthreads();

    const float zq  = cb[(size_t)widx * EED + t];
    const float zev = zs[t];
    g_zqst[row * EED + t] = zev + (zq - zev);
    const float df = zq - zev;
    bd[t] = df * df;
    __syncthreads();
    for (int o = 64; o > 0; o >>= 1) {
        if (t < o) bd[t] += bd[t + o];
        __syncthreads();
    }
    if (t == 0) {
        g_idx[row] = widx;
        g_lossrow[row] = bd[0];
        atomicAdd(&g_hist[widx], 1.0f);
    }
}

// ---------------- final 2-wide head ----------------
__global__ __launch_bounds__(128) void head_kernel(
    const float* __restrict__ Wd3, const float* __restrict__ bd3,
    float* __restrict__ out, int out_size)
{
    const int row = blockIdx.x, t = threadIdx.x;
    __shared__ float sred[4];
    const float x = g_d2[row * EED + t];
    for (int c = 0; c < 2; ++c) {
        float p = x * Wd3[c * EED + t];
#pragma unroll
        for (int o = 16; o > 0; o >>= 1) p += __shfl_xor_sync(0xffffffffu, p, o);
        if ((t & 31) == 0) sred[t >> 5] = p;
        __syncthreads();
        if (t == 0) {
            float tot = sred[0] + sred[1] + sred[2] + sred[3];
            int oi = row * 2 + c;
            if (oi < out_size) out[oi] = tot + bd3[c];
        }
        __syncthreads();
    }
}

__global__ void idx_copy_kernel(float* out, int out_size) {
    int i = blockIdx.x * blockDim.x + threadIdx.x;
    if (i < BB) {
        int oi = 2 * BB + i;
        if (oi < out_size) out[oi] = (float)g_idx[i];
    }
}

__global__ __launch_bounds__(1024) void finalize_kernel(float* out, int out_size) {
    const int t = threadIdx.x;
    __shared__ float sh[1024];

    float p = g_hist[t] * (1.f / 2048.f);
    sh[t] = p * logf(p + 1e-10f);
    __syncthreads();
    for (int o = 512; o > 0; o >>= 1) {
        if (t < o) sh[t] += sh[t + o];
        __syncthreads();
    }
    const float perp = expf(-sh[0]);
    __syncthreads();

    sh[t] = g_lossrow[t] + g_lossrow[t + 1024];
    __syncthreads();
    for (int o = 512; o > 0; o >>= 1) {
        if (t < o) sh[t] += sh[t + o];
        __syncthreads();
    }
    if (t == 0) {
        int li = 2 * BB + BB;
        if (li < out_size)     out[li]     = 0.1f * sh[0] / (float)(BB * EED);
        if (li + 1 < out_size) out[li + 1] = perp;
    }
}

// ---------------- launch ----------------
extern "C" void kernel_launch(void* const* d_in, const int* in_sizes, int n_in,
                              void* d_out, int out_size)
{
    const float* x         = (const float*)d_in[0];
    const float* W_in      = (const float*)d_in[1];
    const float* b_in      = (const float*)d_in[2];
    const float* cls_token = (const float*)d_in[3];
    const float* Wqkv      = (const float*)d_in[4];
    const float* bqkv      = (const float*)d_in[5];
    const float* Wo        = (const float*)d_in[6];
    const float* bo        = (const float*)d_in[7];
    const float* W1        = (const float*)d_in[8];
    const float* b1        = (const float*)d_in[9];
    const float* W2        = (const float*)d_in[10];
    const float* b2        = (const float*)d_in[11];
    const float* ln1_g     = (const float*)d_in[12];
    const float* ln1_b     = (const float*)d_in[13];
    const float* ln2_g     = (const float*)d_in[14];
    const float* ln2_b     = (const float*)d_in[15];
    const float* lnf_g     = (const float*)d_in[16];
    const float* lnf_b     = (const float*)d_in[17];
    const float* W_out     = (const float*)d_in[18];
    const float* b_out     = (const float*)d_in[19];
    const float* codebook  = (const float*)d_in[20];
    const float* Wd1       = (const float*)d_in[21];
    const float* bd1       = (const float*)d_in[22];
    const float* lnd_g     = (const float*)d_in[23];
    const float* lnd_b     = (const float*)d_in[24];
    const float* Wd2       = (const float*)d_in[25];
    const float* bd2       = (const float*)d_in[26];
    const float* Wd3       = (const float*)d_in[27];
    const float* bd3       = (const float*)d_in[28];
    float* out = (float*)d_out;

    float *p_h, *p_qkv, *p_o, *p_ff, *p_cls, *p_ze, *p_zqst, *p_d1, *p_d2, *p_xpad;
    float *p_wi_h, *p_wi_l, *p_wq_h, *p_wq_l, *p_wo_h, *p_wo_l;
    float *p_w1_h, *p_w1_l, *p_w2_h, *p_w2_l;
    float *p_wout_h, *p_wout_l, *p_wd1_h, *p_wd1_l, *p_wd2_h, *p_wd2_l;
    cudaGetSymbolAddress((void**)&p_h,    g_h);
    cudaGetSymbolAddress((void**)&p_qkv,  g_qkv);
    cudaGetSymbolAddress((void**)&p_o,    g_o);
    cudaGetSymbolAddress((void**)&p_ff,   g_ff);
    cudaGetSymbolAddress((void**)&p_cls,  g_cls);
    cudaGetSymbolAddress((void**)&p_ze,   g_ze);
    cudaGetSymbolAddress((void**)&p_zqst, g_zqst);
    cudaGetSymbolAddress((void**)&p_d1,   g_d1);
    cudaGetSymbolAddress((void**)&p_d2,   g_d2);
    cudaGetSymbolAddress((void**)&p_xpad, g_xpad);
    cudaGetSymbolAddress((void**)&p_wi_h, g_wi_h);
    cudaGetSymbolAddress((void**)&p_wi_l, g_wi_l);
    cudaGetSymbolAddress((void**)&p_wq_h, g_wq_h);
    cudaGetSymbolAddress((void**)&p_wq_l, g_wq_l);
    cudaGetSymbolAddress((void**)&p_wo_h, g_wo_h);
    cudaGetSymbolAddress((void**)&p_wo_l, g_wo_l);
    cudaGetSymbolAddress((void**)&p_w1_h, g_w1_h);
    cudaGetSymbolAddress((void**)&p_w1_l, g_w1_l);
    cudaGetSymbolAddress((void**)&p_w2_h, g_w2_h);
    cudaGetSymbolAddress((void**)&p_w2_l, g_w2_l);
    cudaGetSymbolAddress((void**)&p_wout_h, g_wout_h);
    cudaGetSymbolAddress((void**)&p_wout_l, g_wout_l);
    cudaGetSymbolAddress((void**)&p_wd1_h, g_wd1_h);
    cudaGetSymbolAddress((void**)&p_wd1_l, g_wd1_l);
    cudaGetSymbolAddress((void**)&p_wd2_h, g_wd2_h);
    cudaGetSymbolAddress((void**)&p_wd2_l, g_wd2_l);

    const int MTOK = BB * SS;        // 131072
    const int MALL = BB * TTT;       // 133120
    const int SMEM = 6 * 128 * 20 * 4;  // 61440 bytes dynamic

    cudaFuncSetAttribute(gemm_tc<0>, cudaFuncAttributeMaxDynamicSharedMemorySize, SMEM);
    cudaFuncSetAttribute(gemm_tc<1>, cudaFuncAttributeMaxDynamicSharedMemorySize, SMEM);
    cudaFuncSetAttribute(gemm_tc<2>, cudaFuncAttributeMaxDynamicSharedMemorySize, SMEM);
    cudaFuncSetAttribute(gemm_tc<3>, cudaFuncAttributeMaxDynamicSharedMemorySize, SMEM);

    {
        int n = out_size > KKC ? out_size : KKC;
        zero_kernel<<<(n + 255) / 256, 256>>>(out, out_size);
    }
    pe_init_kernel<<<(SS * DD + 255) / 256, 256>>>();
    cls_fill_kernel<<<(BB * DD + 255) / 256, 256>>>(cls_token);

    // ---- prep: pad x, split all weights into tf32 hi/lo planes ----
    pad_x_kernel<<<(BB * SS * CCP + 255) / 256, 256>>>(x);
    auto splitw = [&](const float* in, float* oh, float* ol, int N, int K, int Kp) {
        splitw_kernel<<<(N * Kp + 255) / 256, 256>>>(in, oh, ol, N, K, Kp);
    };
    splitw(W_in,  p_wi_h,  p_wi_l,  DD, CC, CCP);
    splitw(Wqkv,  p_wq_h,  p_wq_l,  LLY * 3 * DD, DD, DD);
    splitw(Wo,    p_wo_h,  p_wo_l,  LLY * DD, DD, DD);
    splitw(W1,    p_w1_h,  p_w1_l,  LLY * FFD, DD, DD);
    splitw(W2,    p_w2_h,  p_w2_l,  LLY * DD, FFD, FFD);
    splitw(W_out, p_wout_h, p_wout_l, EED, DD, DD);
    splitw(Wd1,   p_wd1_h, p_wd1_l, DD, EED, EED);
    splitw(Wd2,   p_wd2_h, p_wd2_l, EED, DD, DD);

    // ---- input projection + PE, scattered into h rows (skipping cls rows) ----
    gemm_tc<3><<<dim3(MTOK / 128, DD / 128), 256, SMEM>>>(
        p_xpad, p_wi_h, p_wi_l, b_in, nullptr, p_h, MTOK, DD, CCP, CCP);

    for (int l = 0; l < LLY; ++l) {
        gemm_tc<0><<<dim3(MALL / 128, (3 * DD) / 128), 256, SMEM>>>(
            p_h, p_wq_h + (size_t)l * 3 * DD * DD, p_wq_l + (size_t)l * 3 * DD * DD,
            bqkv + (size_t)l * 3 * DD, nullptr, p_qkv, MALL, 3 * DD, DD, DD);
        attn_kernel<<<BB * HHD, 256>>>();
        gemm_tc<2><<<dim3(MALL / 128, DD / 128), 256, SMEM>>>(
            p_o, p_wo_h + (size_t)l * DD * DD, p_wo_l + (size_t)l * DD * DD,
            bo + (size_t)l * DD, p_h, p_h, MALL, DD, DD, DD);
        ln_kernel<0><<<MALL / 8, 256>>>(p_h, p_h, ln1_g + l * DD, ln1_b + l * DD, DD, DD);
        gemm_tc<1><<<dim3(MALL / 128, FFD / 128), 256, SMEM>>>(
            p_h, p_w1_h + (size_t)l * FFD * DD, p_w1_l + (size_t)l * FFD * DD,
            b1 + (size_t)l * FFD, nullptr, p_ff, MALL, FFD, DD, DD);
        gemm_tc<2><<<dim3(MALL / 128, DD / 128), 256, SMEM>>>(
            p_ff, p_w2_h + (size_t)l * DD * FFD, p_w2_l + (size_t)l * DD * FFD,
            b2 + (size_t)l * DD, p_h, p_h, MALL, DD, FFD, FFD);
        ln_kernel<0><<<MALL / 8, 256>>>(p_h, p_h, ln2_g + l * DD, ln2_b + l * DD, DD, DD);
    }

    // cls row LN -> z_e
    ln_kernel<0><<<BB / 8, 256>>>(p_h, p_cls, lnf_g, lnf_b, (size_t)TTT * DD, DD);
    gemm_tc<0><<<dim3(BB / 128, EED / 128), 256, SMEM>>>(
        p_cls, p_wout_h, p_wout_l, b_out, nullptr, p_ze, BB, EED, DD, DD);

    // VQ
    vq_kernel<<<BB, 128>>>(codebook);

    // decoder
    gemm_tc<0><<<dim3(BB / 128, DD / 128), 256, SMEM>>>(
        p_zqst, p_wd1_h, p_wd1_l, bd1, nullptr, p_d1, BB, DD, EED, EED);
    ln_kernel<1><<<BB / 8, 256>>>(p_d1, p_d1, lnd_g, lnd_b, DD, DD);
    gemm_tc<1><<<dim3(BB / 128, EED / 128), 256, SMEM>>>(
        p_d1, p_wd2_h, p_wd2_l, bd2, nullptr, p_d2, BB, EED, DD, DD);
    head_kernel<<<BB, 128>>>(Wd3, bd3, out, out_size);

    idx_copy_kernel<<<(BB + 255) / 256, 256>>>(out, out_size);
    finalize_kernel<<<1, 1024>>>(out, out_size);
}

// round 15
// speedup vs baseline: 1.7913x; 1.2630x over previous
#include <cuda_runtime.h>
#include <cuda_bf16.h>
#include <math.h>
#include <stdint.h>

// ---------------- problem constants ----------------
constexpr int BB  = 2048;
constexpr int SS  = 64;
constexpr int CC  = 142;
constexpr int CCP = 144;  // padded K for input projection (16-float multiple)
constexpr int DD  = 256;
constexpr int HHD = 8;
constexpr int DHH = 32;
constexpr int FFD = 512;
constexpr int LLY = 3;
constexpr int EED = 128;
constexpr int KKC = 1024;
constexpr int TTT = 65;
#define EPSLN 1e-5f

// ---------------- scratch (device globals; no allocs allowed) ----------------
__device__ float g_h   [(size_t)BB * TTT * DD];
__device__ float g_qkv [(size_t)BB * TTT * 3 * DD];
__device__ float g_o   [(size_t)BB * TTT * DD];
__device__ float g_ff  [(size_t)BB * TTT * FFD];
__device__ float g_cls [BB * DD];
__device__ float g_ze  [BB * EED];
__device__ float g_zqst[BB * EED];
__device__ float g_d1  [BB * DD];
__device__ float g_d2  [BB * EED];
__device__ float g_lossrow[BB];
__device__ float g_hist[KKC];
__device__ int   g_idx [BB];
__device__ float g_pe  [SS * DD];

// padded input + pre-split bf16 weight planes
__device__ float g_xpad [(size_t)BB * SS * CCP];
__device__ __nv_bfloat16 g_wi_h [DD * CCP];
__device__ __nv_bfloat16 g_wi_l [DD * CCP];
__device__ __nv_bfloat16 g_wq_h [LLY * 3 * DD * DD];
__device__ __nv_bfloat16 g_wq_l [LLY * 3 * DD * DD];
__device__ __nv_bfloat16 g_wo_h [LLY * DD * DD];
__device__ __nv_bfloat16 g_wo_l [LLY * DD * DD];
__device__ __nv_bfloat16 g_w1_h [LLY * FFD * DD];
__device__ __nv_bfloat16 g_w1_l [LLY * FFD * DD];
__device__ __nv_bfloat16 g_w2_h [LLY * DD * FFD];
__device__ __nv_bfloat16 g_w2_l [LLY * DD * FFD];
__device__ __nv_bfloat16 g_wout_h [EED * DD];
__device__ __nv_bfloat16 g_wout_l [EED * DD];
__device__ __nv_bfloat16 g_wd1_h [DD * EED];
__device__ __nv_bfloat16 g_wd1_l [DD * EED];
__device__ __nv_bfloat16 g_wd2_h [EED * DD];
__device__ __nv_bfloat16 g_wd2_l [EED * DD];

// ---------------- helpers ----------------
__device__ __forceinline__ float gelu_exact(float v) {
    return 0.5f * v * (1.f + erff(v * 0.70710678118654752f));
}

// split a pair of fp32 into packed bf16 hi/lo pairs (lo-lane = first element)
__device__ __forceinline__ void splitb(float2 p, uint32_t& h, uint32_t& l) {
    uint32_t hh;
    asm("cvt.rn.bf16x2.f32 %0, %1, %2;" : "=r"(hh) : "f"(p.y), "f"(p.x));
    float r0 = p.x - __uint_as_float(hh << 16);
    float r1 = p.y - __uint_as_float(hh & 0xffff0000u);
    asm("cvt.rn.bf16x2.f32 %0, %1, %2;" : "=r"(l) : "f"(r1), "f"(r0));
    h = hh;
}

__device__ __forceinline__ void mma16816(float* d, const uint32_t* a, const uint32_t* b) {
    asm volatile(
        "mma.sync.aligned.m16n8k16.row.col.f32.bf16.bf16.f32 "
        "{%0,%1,%2,%3}, {%4,%5,%6,%7}, {%8,%9}, {%0,%1,%2,%3};"
        : "+f"(d[0]), "+f"(d[1]), "+f"(d[2]), "+f"(d[3])
        : "r"(a[0]), "r"(a[1]), "r"(a[2]), "r"(a[3]), "r"(b[0]), "r"(b[1]));
}

__device__ __forceinline__ void cp16(uint32_t dst, const void* src) {
    asm volatile("cp.async.cg.shared.global [%0], [%1], 16;\n"
                 :: "r"(dst), "l"(src) : "memory");
}
__device__ __forceinline__ void cp_async_commit() {
    asm volatile("cp.async.commit_group;\n" ::: "memory");
}
__device__ __forceinline__ void cp_async_wait0() {
    asm volatile("cp.async.wait_group 0;\n" ::: "memory");
}

// ---------------- prep kernels ----------------
__global__ void pad_x_kernel(const float* __restrict__ x) {
    int i = blockIdx.x * blockDim.x + threadIdx.x;
    if (i < BB * SS * CCP) {
        int r = i / CCP, c = i - r * CCP;
        g_xpad[i] = (c < CC) ? x[(size_t)r * CC + c] : 0.f;
    }
}

// split weight (N x K raw fp32) into bf16 hi/lo planes (N x Kp), zero-padded
__global__ void splitw_kernel(const float* __restrict__ in,
                              __nv_bfloat16* __restrict__ oh, __nv_bfloat16* __restrict__ ol,
                              int N, int K, int Kp) {
    int i = blockIdx.x * blockDim.x + threadIdx.x;
    if (i < N * Kp) {
        int r = i / Kp, c = i - r * Kp;
        float v = (c < K) ? in[(size_t)r * K + c] : 0.f;
        __nv_bfloat16 h = __float2bfloat16(v);
        oh[i] = h;
        ol[i] = __float2bfloat16(v - __bfloat162float(h));
    }
}

// ---------------- misc init ----------------
__global__ void pe_init_kernel() {
    int i = blockIdx.x * blockDim.x + threadIdx.x;
    if (i < SS * DD) {
        int s = i >> 8, n = i & 255;
        double div = exp((double)(n & ~1) * (-9.210340371976184 / 256.0));
        double v = (n & 1) ? cos((double)s * div) : sin((double)s * div);
        g_pe[i] = (float)v;
    }
}

__global__ void zero_kernel(float* out, int out_size) {
    int i = blockIdx.x * blockDim.x + threadIdx.x;
    if (i < out_size) out[i] = 0.f;
    if (i < KKC) g_hist[i] = 0.f;
}

__global__ void cls_fill_kernel(const float* __restrict__ cls) {
    int i = blockIdx.x * blockDim.x + threadIdx.x;
    if (i < BB * DD) {
        int b = i >> 8, d = i & 255;
        g_h[(size_t)b * TTT * DD + d] = cls[d];
    }
}

// ---------------- 3xBF16 tensor-core GEMM (m16n8k16), pre-split B planes ----------------
// C = A[M,lda] * B[N,ldb]^T + bias. A fp32 in smem (split at consume); B bf16 hi/lo planes.
// CTA tile 128x128, BK=16, 8 warps (4m x 2n).
// smem: A 2 stages [128][20] fp32; Bh,Bl 2 stages [128][24] bf16.
template <int EPI>
__global__ __launch_bounds__(256, 2) void gemm_tc(
    const float* __restrict__ A,
    const __nv_bfloat16* __restrict__ Bh, const __nv_bfloat16* __restrict__ Bl,
    const float* __restrict__ bias, const float* __restrict__ resid,
    float* __restrict__ C, int M, int N, int Kp, int lda)
{
    extern __shared__ char dsmc[];
    float* Asm = (float*)dsmc;                        // 2 x 128 x 20 fp32 = 20480 B
    char*  BhS = dsmc + 20480;                        // 2 x 128 x 24 bf16 = 12288 B
    char*  BlS = dsmc + 32768;                        // 2 x 128 x 24 bf16 = 12288 B

    const int tid  = threadIdx.x;
    const int warp = tid >> 5, lane = tid & 31;
    const int g    = lane >> 2;
    const int tg   = lane & 3;
    const int wm   = (warp >> 1) * 32;
    const int wn   = (warp & 1) * 64;
    const int m0   = blockIdx.x * 128, n0 = blockIdx.y * 128;
    const int ldb  = Kp;

    float acc[2][8][4];
#pragma unroll
    for (int i = 0; i < 2; ++i)
#pragma unroll
        for (int j = 0; j < 8; ++j)
#pragma unroll
            for (int c = 0; c < 4; ++c) acc[i][j][c] = 0.f;

    const uint32_t sA  = (uint32_t)__cvta_generic_to_shared(Asm);
    const uint32_t sBh = (uint32_t)__cvta_generic_to_shared(BhS);
    const uint32_t sBl = (uint32_t)__cvta_generic_to_shared(BlS);
    const uint32_t A_STAGE = 128 * 20 * 4;   // 10240
    const uint32_t B_STAGE = 128 * 24 * 2;   // 6144

    auto fill = [&](int stage, int k0) {
        const uint32_t dA  = sA  + stage * A_STAGE;
        const uint32_t dBh = sBh + stage * B_STAGE;
        const uint32_t dBl = sBl + stage * B_STAGE;
        // A: 512 x 16B chunks (fp32), 2 per thread
#pragma unroll
        for (int c = 0; c < 2; ++c) {
            const int chunk = tid + c * 256;
            const int row = chunk >> 2;
            const int kl  = (chunk & 3) * 4;
            cp16(dA + (uint32_t)(row * 20 + kl) * 4,
                 A + (size_t)(m0 + row) * lda + k0 + kl);
        }
        // B planes: 256 x 16B chunks (bf16, 8 halves per chunk), 1 per thread per plane
        {
            const int row  = tid >> 1;
            const int half = tid & 1;
            const uint32_t doff = (uint32_t)(row * 24 + half * 8) * 2;
            const size_t soff = (size_t)(n0 + row) * ldb + k0 + half * 8;
            cp16(dBh + doff, Bh + soff);
            cp16(dBl + doff, Bl + soff);
        }
    };

    const int NT = Kp >> 4;

    fill(0, 0);
    cp_async_commit();
    cp_async_wait0();
    __syncthreads();

    for (int t = 0; t < NT; ++t) {
        const int cur = t & 1;
        if (t + 1 < NT) {
            fill((t + 1) & 1, (t + 1) * 16);
            cp_async_commit();
        }

        const float* Ac  = Asm + cur * 2560;
        const char*  Bhc = BhS + cur * B_STAGE;
        const char*  Blc = BlS + cur * B_STAGE;

        // A fragments for both m-tiles: 4 packed-pair regs each (hi and lo planes)
        uint32_t ah[2][4], al[2][4];
#pragma unroll
        for (int mt = 0; mt < 2; ++mt) {
            const int mr = wm + mt * 16;
            float2 p0 = *(const float2*)&Ac[(mr + g    ) * 20 + 2 * tg    ];
            float2 p1 = *(const float2*)&Ac[(mr + g + 8) * 20 + 2 * tg    ];
            float2 p2 = *(const float2*)&Ac[(mr + g    ) * 20 + 2 * tg + 8];
            float2 p3 = *(const float2*)&Ac[(mr + g + 8) * 20 + 2 * tg + 8];
            splitb(p0, ah[mt][0], al[mt][0]);
            splitb(p1, ah[mt][1], al[mt][1]);
            splitb(p2, ah[mt][2], al[mt][2]);
            splitb(p3, ah[mt][3], al[mt][3]);
        }

        // nt in groups of 4, pass-major (distinct accumulators between chained MMAs)
#pragma unroll
        for (int half = 0; half < 2; ++half) {
            uint32_t bh[4][2], bl[4][2];
#pragma unroll
            for (int j = 0; j < 4; ++j) {
                const int nc = wn + (half * 4 + j) * 8;
                const uint32_t off0 = (uint32_t)((nc + g) * 24 + 2 * tg) * 2;
                bh[j][0] = *(const uint32_t*)(Bhc + off0);
                bh[j][1] = *(const uint32_t*)(Bhc + off0 + 16);
                bl[j][0] = *(const uint32_t*)(Blc + off0);
                bl[j][1] = *(const uint32_t*)(Blc + off0 + 16);
            }
#pragma unroll
            for (int j = 0; j < 4; ++j)
#pragma unroll
                for (int mt = 0; mt < 2; ++mt)
                    mma16816(acc[mt][half * 4 + j], ah[mt], bh[j]);   // hi * hi
#pragma unroll
            for (int j = 0; j < 4; ++j)
#pragma unroll
                for (int mt = 0; mt < 2; ++mt)
                    mma16816(acc[mt][half * 4 + j], ah[mt], bl[j]);   // hi * lo
#pragma unroll
            for (int j = 0; j < 4; ++j)
#pragma unroll
                for (int mt = 0; mt < 2; ++mt)
                    mma16816(acc[mt][half * 4 + j], al[mt], bh[j]);   // lo * hi
        }

        if (t + 1 < NT) cp_async_wait0();
        __syncthreads();
    }

    // epilogue (accumulator layout identical to m16n8k8 version)
#pragma unroll
    for (int mt = 0; mt < 2; ++mt) {
#pragma unroll
        for (int nt = 0; nt < 8; ++nt) {
#pragma unroll
            for (int c = 0; c < 4; ++c) {
                const int m = m0 + wm + mt * 16 + g + ((c >> 1) ? 8 : 0);
                const int n = n0 + wn + nt * 8 + 2 * tg + (c & 1);
                float v = acc[mt][nt][c] + bias[n];
                if (EPI == 1) {
                    C[(size_t)m * N + n] = gelu_exact(v);
                } else if (EPI == 2) {
                    v += resid[(size_t)m * N + n];
                    C[(size_t)m * N + n] = v;
                } else if (EPI == 3) {
                    const int bi = m >> 6;
                    const int s  = m & 63;
                    v += g_pe[s * DD + n];
                    C[(size_t)(m + bi + 1) * N + n] = v;
                } else {
                    C[(size_t)m * N + n] = v;
                }
            }
        }
    }
}

// ---------------- attention: warp-parallel, block per (b, head) ----------------
__global__ __launch_bounds__(256) void attn_kernel() {
    const int bh = blockIdx.x;
    const int b = bh >> 3, hd = bh & 7;
    __shared__ float Qs[TTT][DHH + 1];
    __shared__ float Ks[TTT][DHH + 1];
    __shared__ float Vs[TTT][DHH + 1];
    __shared__ float Ps[8][TTT + 1];
    const int tid = threadIdx.x;
    const int w = tid >> 5, l = tid & 31;
    const size_t base = (size_t)b * TTT * 768;

    for (int i = tid; i < TTT * DHH; i += 256) {
        int t = i >> 5, d = i & 31;
        size_t rb = base + (size_t)t * 768 + hd * 32 + d;
        Qs[t][d] = g_qkv[rb];
        Ks[t][d] = g_qkv[rb + 256];
        Vs[t][d] = g_qkv[rb + 512];
    }
    __syncthreads();

    for (int qi = w; qi < TTT; qi += 8) {
        float q[DHH];
#pragma unroll
        for (int d = 0; d < DHH; ++d) q[d] = Qs[qi][d];

        float s0 = 0.f, s1 = 0.f, s2 = 0.f;
#pragma unroll
        for (int d = 0; d < DHH; ++d) {
            s0 = fmaf(q[d], Ks[l][d], s0);
            s1 = fmaf(q[d], Ks[l + 32][d], s1);
        }
        if (l == 0) {
#pragma unroll
            for (int d = 0; d < DHH; ++d) s2 = fmaf(q[d], Ks[64][d], s2);
        }
        const float scale = 0.17677669529663687f;   // 1/sqrt(32)
        s0 *= scale; s1 *= scale; s2 *= scale;

        float mx = fmaxf(s0, s1);
        if (l == 0) mx = fmaxf(mx, s2);
#pragma unroll
        for (int o = 16; o > 0; o >>= 1) mx = fmaxf(mx, __shfl_xor_sync(0xffffffffu, mx, o));

        float e0 = expf(s0 - mx);
        float e1 = expf(s1 - mx);
        float e2 = (l == 0) ? expf(s2 - mx) : 0.f;
        float sum = e0 + e1 + e2;
#pragma unroll
        for (int o = 16; o > 0; o >>= 1) sum += __shfl_xor_sync(0xffffffffu, sum, o);
        const float inv = 1.f / sum;

        Ps[w][l]      = e0 * inv;
        Ps[w][l + 32] = e1 * inv;
        if (l == 0) Ps[w][64] = e2 * inv;
        __syncwarp();

        float acc = 0.f;
#pragma unroll 5
        for (int ki = 0; ki < TTT; ++ki)
            acc = fmaf(Ps[w][ki], Vs[ki][l], acc);

        g_o[((size_t)b * TTT + qi) * DD + hd * 32 + l] = acc;
        __syncwarp();
    }
}

// ---------------- LayerNorm: warp per row, 8 rows per block, shfl-only ----------------
template <int GELU>
__global__ __launch_bounds__(256) void ln_kernel(
    const float* __restrict__ in, float* __restrict__ out,
    const float* __restrict__ gamma, const float* __restrict__ beta,
    size_t inStride, size_t outStride)
{
    const int w = threadIdx.x >> 5, l = threadIdx.x & 31;
    const size_t row = (size_t)blockIdx.x * 8 + w;
    const float* rp = in + row * inStride;

    float4 a = *(const float4*)(rp + l * 4);
    float4 c = *(const float4*)(rp + 128 + l * 4);

    float s = a.x + a.y + a.z + a.w + c.x + c.y + c.z + c.w;
#pragma unroll
    for (int o = 16; o > 0; o >>= 1) s += __shfl_xor_sync(0xffffffffu, s, o);
    const float mean = s * (1.f / 256.f);

    a.x -= mean; a.y -= mean; a.z -= mean; a.w -= mean;
    c.x -= mean; c.y -= mean; c.z -= mean; c.w -= mean;
    float s2 = a.x * a.x + a.y * a.y + a.z * a.z + a.w * a.w
             + c.x * c.x + c.y * c.y + c.z * c.z + c.w * c.w;
#pragma unroll
    for (int o = 16; o > 0; o >>= 1) s2 += __shfl_xor_sync(0xffffffffu, s2, o);
    const float r = rsqrtf(s2 * (1.f / 256.f) + EPSLN);

    float4 ga = *(const float4*)(gamma + l * 4);
    float4 gc = *(const float4*)(gamma + 128 + l * 4);
    float4 ba = *(const float4*)(beta + l * 4);
    float4 bc = *(const float4*)(beta + 128 + l * 4);

    float4 ya, yc;
    ya.x = a.x * r * ga.x + ba.x;  ya.y = a.y * r * ga.y + ba.y;
    ya.z = a.z * r * ga.z + ba.z;  ya.w = a.w * r * ga.w + ba.w;
    yc.x = c.x * r * gc.x + bc.x;  yc.y = c.y * r * gc.y + bc.y;
    yc.z = c.z * r * gc.z + bc.z;  yc.w = c.w * r * gc.w + bc.w;

    if (GELU) {
        ya.x = gelu_exact(ya.x); ya.y = gelu_exact(ya.y);
        ya.z = gelu_exact(ya.z); ya.w = gelu_exact(ya.w);
        yc.x = gelu_exact(yc.x); yc.y = gelu_exact(yc.y);
        yc.z = gelu_exact(yc.z); yc.w = gelu_exact(yc.w);
    }

    float* op = out + row * outStride;
    *(float4*)(op + l * 4) = ya;
    *(float4*)(op + 128 + l * 4) = yc;
}

// ---------------- VQ ----------------
__global__ __launch_bounds__(128) void vq_kernel(const float* __restrict__ cb) {
    const int row = blockIdx.x, t = threadIdx.x;
    __shared__ float zs[EED];
    __shared__ float bd[128];
    __shared__ int   bi[128];

    zs[t] = g_ze[row * EED + t];
    __syncthreads();

    float ze2 = 0.f;
    for (int d = 0; d < EED; ++d) ze2 = fmaf(zs[d], zs[d], ze2);

    float best = 3.4e38f;
    int bestk = 0;
    for (int k = t; k < KKC; k += 128) {
        const float* c = cb + (size_t)k * EED;
        float dot = 0.f, c2 = 0.f;
        for (int d = 0; d < EED; ++d) {
            float cv = c[d];
            dot = fmaf(cv, zs[d], dot);
            c2  = fmaf(cv, cv, c2);
        }
        float d2 = (ze2 - 2.f * dot) + c2;
        if (d2 < best) { best = d2; bestk = k; }
    }
    bd[t] = best; bi[t] = bestk;
    __syncthreads();
    for (int o = 64; o > 0; o >>= 1) {
        if (t < o) {
            float ob = bd[t + o]; int oi = bi[t + o];
            if (ob < bd[t] || (ob == bd[t] && oi < bi[t])) { bd[t] = ob; bi[t] = oi; }
        }
        __syncthreads();
    }
    const int widx = bi[0];
    __syncthreads();

    const float zq  = cb[(size_t)widx * EED + t];
    const float zev = zs[t];
    g_zqst[row * EED + t] = zev + (zq - zev);
    const float df = zq - zev;
    bd[t] = df * df;
    __syncthreads();
    for (int o = 64; o > 0; o >>= 1) {
        if (t < o) bd[t] += bd[t + o];
        __syncthreads();
    }
    if (t == 0) {
        g_idx[row] = widx;
        g_lossrow[row] = bd[0];
        atomicAdd(&g_hist[widx], 1.0f);
    }
}

// ---------------- final 2-wide head ----------------
__global__ __launch_bounds__(128) void head_kernel(
    const float* __restrict__ Wd3, const float* __restrict__ bd3,
    float* __restrict__ out, int out_size)
{
    const int row = blockIdx.x, t = threadIdx.x;
    __shared__ float sred[4];
    const float x = g_d2[row * EED + t];
    for (int c = 0; c < 2; ++c) {
        float p = x * Wd3[c * EED + t];
#pragma unroll
        for (int o = 16; o > 0; o >>= 1) p += __shfl_xor_sync(0xffffffffu, p, o);
        if ((t & 31) == 0) sred[t >> 5] = p;
        __syncthreads();
        if (t == 0) {
            float tot = sred[0] + sred[1] + sred[2] + sred[3];
            int oi = row * 2 + c;
            if (oi < out_size) out[oi] = tot + bd3[c];
        }
        __syncthreads();
    }
}

__global__ void idx_copy_kernel(float* out, int out_size) {
    int i = blockIdx.x * blockDim.x + threadIdx.x;
    if (i < BB) {
        int oi = 2 * BB + i;
        if (oi < out_size) out[oi] = (float)g_idx[i];
    }
}

__global__ __launch_bounds__(1024) void finalize_kernel(float* out, int out_size) {
    const int t = threadIdx.x;
    __shared__ float sh[1024];

    float p = g_hist[t] * (1.f / 2048.f);
    sh[t] = p * logf(p + 1e-10f);
    __syncthreads();
    for (int o = 512; o > 0; o >>= 1) {
        if (t < o) sh[t] += sh[t + o];
        __syncthreads();
    }
    const float perp = expf(-sh[0]);
    __syncthreads();

    sh[t] = g_lossrow[t] + g_lossrow[t + 1024];
    __syncthreads();
    for (int o = 512; o > 0; o >>= 1) {
        if (t < o) sh[t] += sh[t + o];
        __syncthreads();
    }
    if (t == 0) {
        int li = 2 * BB + BB;
        if (li < out_size)     out[li]     = 0.1f * sh[0] / (float)(BB * EED);
        if (li + 1 < out_size) out[li + 1] = perp;
    }
}

// ---------------- launch ----------------
extern "C" void kernel_launch(void* const* d_in, const int* in_sizes, int n_in,
                              void* d_out, int out_size)
{
    const float* x         = (const float*)d_in[0];
    const float* W_in      = (const float*)d_in[1];
    const float* b_in      = (const float*)d_in[2];
    const float* cls_token = (const float*)d_in[3];
    const float* Wqkv      = (const float*)d_in[4];
    const float* bqkv      = (const float*)d_in[5];
    const float* Wo        = (const float*)d_in[6];
    const float* bo        = (const float*)d_in[7];
    const float* W1        = (const float*)d_in[8];
    const float* b1        = (const float*)d_in[9];
    const float* W2        = (const float*)d_in[10];
    const float* b2        = (const float*)d_in[11];
    const float* ln1_g     = (const float*)d_in[12];
    const float* ln1_b     = (const float*)d_in[13];
    const float* ln2_g     = (const float*)d_in[14];
    const float* ln2_b     = (const float*)d_in[15];
    const float* lnf_g     = (const float*)d_in[16];
    const float* lnf_b     = (const float*)d_in[17];
    const float* W_out     = (const float*)d_in[18];
    const float* b_out     = (const float*)d_in[19];
    const float* codebook  = (const float*)d_in[20];
    const float* Wd1       = (const float*)d_in[21];
    const float* bd1       = (const float*)d_in[22];
    const float* lnd_g     = (const float*)d_in[23];
    const float* lnd_b     = (const float*)d_in[24];
    const float* Wd2       = (const float*)d_in[25];
    const float* bd2       = (const float*)d_in[26];
    const float* Wd3       = (const float*)d_in[27];
    const float* bd3       = (const float*)d_in[28];
    float* out = (float*)d_out;

    float *p_h, *p_qkv, *p_o, *p_ff, *p_cls, *p_ze, *p_zqst, *p_d1, *p_d2, *p_xpad;
    __nv_bfloat16 *p_wi_h, *p_wi_l, *p_wq_h, *p_wq_l, *p_wo_h, *p_wo_l;
    __nv_bfloat16 *p_w1_h, *p_w1_l, *p_w2_h, *p_w2_l;
    __nv_bfloat16 *p_wout_h, *p_wout_l, *p_wd1_h, *p_wd1_l, *p_wd2_h, *p_wd2_l;
    cudaGetSymbolAddress((void**)&p_h,    g_h);
    cudaGetSymbolAddress((void**)&p_qkv,  g_qkv);
    cudaGetSymbolAddress((void**)&p_o,    g_o);
    cudaGetSymbolAddress((void**)&p_ff,   g_ff);
    cudaGetSymbolAddress((void**)&p_cls,  g_cls);
    cudaGetSymbolAddress((void**)&p_ze,   g_ze);
    cudaGetSymbolAddress((void**)&p_zqst, g_zqst);
    cudaGetSymbolAddress((void**)&p_d1,   g_d1);
    cudaGetSymbolAddress((void**)&p_d2,   g_d2);
    cudaGetSymbolAddress((void**)&p_xpad, g_xpad);
    cudaGetSymbolAddress((void**)&p_wi_h, g_wi_h);
    cudaGetSymbolAddress((void**)&p_wi_l, g_wi_l);
    cudaGetSymbolAddress((void**)&p_wq_h, g_wq_h);
    cudaGetSymbolAddress((void**)&p_wq_l, g_wq_l);
    cudaGetSymbolAddress((void**)&p_wo_h, g_wo_h);
    cudaGetSymbolAddress((void**)&p_wo_l, g_wo_l);
    cudaGetSymbolAddress((void**)&p_w1_h, g_w1_h);
    cudaGetSymbolAddress((void**)&p_w1_l, g_w1_l);
    cudaGetSymbolAddress((void**)&p_w2_h, g_w2_h);
    cudaGetSymbolAddress((void**)&p_w2_l, g_w2_l);
    cudaGetSymbolAddress((void**)&p_wout_h, g_wout_h);
    cudaGetSymbolAddress((void**)&p_wout_l, g_wout_l);
    cudaGetSymbolAddress((void**)&p_wd1_h, g_wd1_h);
    cudaGetSymbolAddress((void**)&p_wd1_l, g_wd1_l);
    cudaGetSymbolAddress((void**)&p_wd2_h, g_wd2_h);
    cudaGetSymbolAddress((void**)&p_wd2_l, g_wd2_l);

    const int MTOK = BB * SS;        // 131072
    const int MALL = BB * TTT;       // 133120
    const int SMEM = 20480 + 2 * 12288;  // 45056 bytes dynamic

    cudaFuncSetAttribute(gemm_tc<0>, cudaFuncAttributeMaxDynamicSharedMemorySize, SMEM);
    cudaFuncSetAttribute(gemm_tc<1>, cudaFuncAttributeMaxDynamicSharedMemorySize, SMEM);
    cudaFuncSetAttribute(gemm_tc<2>, cudaFuncAttributeMaxDynamicSharedMemorySize, SMEM);
    cudaFuncSetAttribute(gemm_tc<3>, cudaFuncAttributeMaxDynamicSharedMemorySize, SMEM);

    {
        int n = out_size > KKC ? out_size : KKC;
        zero_kernel<<<(n + 255) / 256, 256>>>(out, out_size);
    }
    pe_init_kernel<<<(SS * DD + 255) / 256, 256>>>();
    cls_fill_kernel<<<(BB * DD + 255) / 256, 256>>>(cls_token);

    // ---- prep: pad x, split all weights into bf16 hi/lo planes ----
    pad_x_kernel<<<(BB * SS * CCP + 255) / 256, 256>>>(x);
    auto splitw = [&](const float* in, __nv_bfloat16* oh, __nv_bfloat16* ol, int N, int K, int Kp) {
        splitw_kernel<<<(N * Kp + 255) / 256, 256>>>(in, oh, ol, N, K, Kp);
    };
    splitw(W_in,  p_wi_h,  p_wi_l,  DD, CC, CCP);
    splitw(Wqkv,  p_wq_h,  p_wq_l,  LLY * 3 * DD, DD, DD);
    splitw(Wo,    p_wo_h,  p_wo_l,  LLY * DD, DD, DD);
    splitw(W1,    p_w1_h,  p_w1_l,  LLY * FFD, DD, DD);
    splitw(W2,    p_w2_h,  p_w2_l,  LLY * DD, FFD, FFD);
    splitw(W_out, p_wout_h, p_wout_l, EED, DD, DD);
    splitw(Wd1,   p_wd1_h, p_wd1_l, DD, EED, EED);
    splitw(Wd2,   p_wd2_h, p_wd2_l, EED, DD, DD);

    // ---- input projection + PE, scattered into h rows (skipping cls rows) ----
    gemm_tc<3><<<dim3(MTOK / 128, DD / 128), 256, SMEM>>>(
        p_xpad, p_wi_h, p_wi_l, b_in, nullptr, p_h, MTOK, DD, CCP, CCP);

    for (int l = 0; l < LLY; ++l) {
        gemm_tc<0><<<dim3(MALL / 128, (3 * DD) / 128), 256, SMEM>>>(
            p_h, p_wq_h + (size_t)l * 3 * DD * DD, p_wq_l + (size_t)l * 3 * DD * DD,
            bqkv + (size_t)l * 3 * DD, nullptr, p_qkv, MALL, 3 * DD, DD, DD);
        attn_kernel<<<BB * HHD, 256>>>();
        gemm_tc<2><<<dim3(MALL / 128, DD / 128), 256, SMEM>>>(
            p_o, p_wo_h + (size_t)l * DD * DD, p_wo_l + (size_t)l * DD * DD,
            bo + (size_t)l * DD, p_h, p_h, MALL, DD, DD, DD);
        ln_kernel<0><<<MALL / 8, 256>>>(p_h, p_h, ln1_g + l * DD, ln1_b + l * DD, DD, DD);
        gemm_tc<1><<<dim3(MALL / 128, FFD / 128), 256, SMEM>>>(
            p_h, p_w1_h + (size_t)l * FFD * DD, p_w1_l + (size_t)l * FFD * DD,
            b1 + (size_t)l * FFD, nullptr, p_ff, MALL, FFD, DD, DD);
        gemm_tc<2><<<dim3(MALL / 128, DD / 128), 256, SMEM>>>(
            p_ff, p_w2_h + (size_t)l * DD * FFD, p_w2_l + (size_t)l * DD * FFD,
            b2 + (size_t)l * DD, p_h, p_h, MALL, DD, FFD, FFD);
        ln_kernel<0><<<MALL / 8, 256>>>(p_h, p_h, ln2_g + l * DD, ln2_b + l * DD, DD, DD);
    }

    // cls row LN -> z_e
    ln_kernel<0><<<BB / 8, 256>>>(p_h, p_cls, lnf_g, lnf_b, (size_t)TTT * DD, DD);
    gemm_tc<0><<<dim3(BB / 128, EED / 128), 256, SMEM>>>(
        p_cls, p_wout_h, p_wout_l, b_out, nullptr, p_ze, BB, EED, DD, DD);

    // VQ
    vq_kernel<<<BB, 128>>>(codebook);

    // decoder
    gemm_tc<0><<<dim3(BB / 128, DD / 128), 256, SMEM>>>(
        p_zqst, p_wd1_h, p_wd1_l, bd1, nullptr, p_d1, BB, DD, EED, EED);
    ln_kernel<1><<<BB / 8, 256>>>(p_d1, p_d1, lnd_g, lnd_b, DD, DD);
    gemm_tc<1><<<dim3(BB / 128, EED / 128), 256, SMEM>>>(
        p_d1, p_wd2_h, p_wd2_l, bd2, nullptr, p_d2, BB, EED, DD, DD);
    head_kernel<<<BB, 128>>>(Wd3, bd3, out, out_size);

    idx_copy_kernel<<<(BB + 255) / 256, 256>>>(out, out_size);
    finalize_kernel<<<1, 1024>>>(out, out_size);
}